// round 1
// baseline (speedup 1.0000x reference)
#include <cuda_runtime.h>
#include <cstdint>

#define BSZ 8192
#define CDIM 128
#define DDIM 256
#define TILE 128
#define BK 8

// ---------------- scratch (static device globals; no allocation) ----------------
__device__ float g_sim[(size_t)BSZ * BSZ];   // raw cosine-sim gram (256 MB)
__device__ float g_eud[(size_t)BSZ * BSZ];   // raw euclidean distances (256 MB)
__device__ float g_invn[BSZ];                // 1/(||label_i|| + 1e-12)
__device__ float g_sq[BSZ];                  // ||output_i||^2
__device__ float g_rowloss[BSZ];
__device__ unsigned g_smin_enc, g_smax_enc, g_emax_enc;

// monotone float <-> uint encoding so min/max reduce with integer atomics
__device__ __forceinline__ unsigned fenc(float f) {
    unsigned u = __float_as_uint(f);
    return (u & 0x80000000u) ? ~u : (u | 0x80000000u);
}
__device__ __forceinline__ float fdec(unsigned e) {
    unsigned u = (e & 0x80000000u) ? (e & 0x7FFFFFFFu) : ~e;
    return __uint_as_float(u);
}

// packed f32x2 helpers (Blackwell FFMA2 path: 2x fp32 FMA per instruction)
__device__ __forceinline__ unsigned long long pack_dup(float a) {
    unsigned long long d;
    asm("mov.b64 %0, {%1, %2};" : "=l"(d) : "f"(a), "f"(a));
    return d;
}
__device__ __forceinline__ unsigned long long ffma2(unsigned long long a,
                                                    unsigned long long b,
                                                    unsigned long long c) {
    unsigned long long d;
    asm("fma.rn.f32x2 %0, %1, %2, %3;" : "=l"(d) : "l"(a), "l"(b), "l"(c));
    return d;
}
__device__ __forceinline__ float2 unpack2(unsigned long long v) {
    float2 r;
    asm("mov.b64 {%0, %1}, %2;" : "=f"(r.x), "=f"(r.y) : "l"(v));
    return r;
}

// ---------------- kernel 0: reset global reduction scalars ----------------
__global__ void init_kernel() {
    g_smin_enc = fenc(3.4e38f);
    g_smax_enc = fenc(-3.4e38f);
    g_emax_enc = fenc(0.0f);
}

// ---------------- kernel 1: per-row norms ----------------
__global__ __launch_bounds__(256) void rownorm_kernel(const float* __restrict__ outputs,
                                                      const float* __restrict__ labels) {
    const int row = blockIdx.x;
    const int t = threadIdx.x;
    float l = (t < CDIM) ? labels[(size_t)row * CDIM + t] : 0.0f;
    float lsum = l * l;
    float o = outputs[(size_t)row * DDIM + t];
    float osum = o * o;
    #pragma unroll
    for (int off = 16; off; off >>= 1) {
        lsum += __shfl_xor_sync(0xffffffffu, lsum, off);
        osum += __shfl_xor_sync(0xffffffffu, osum, off);
    }
    __shared__ float sl[8], so[8];
    if ((t & 31) == 0) { sl[t >> 5] = lsum; so[t >> 5] = osum; }
    __syncthreads();
    if (t == 0) {
        float L = 0.0f, O = 0.0f;
        #pragma unroll
        for (int w = 0; w < 8; w++) { L += sl[w]; O += so[w]; }
        g_invn[row] = 1.0f / (sqrtf(L) + 1e-12f);
        g_sq[row] = O;
    }
}

// ---------------- kernel 2: fused upper-triangle grams (sim + eud) ----------------
__global__ __launch_bounds__(256) void gram_kernel(const float* __restrict__ outputs,
                                                   const float* __restrict__ labels) {
    const int bi = blockIdx.y, bj = blockIdx.x;
    if (bj < bi) return;   // symmetric: upper triangle only

    __shared__ float As[BK][TILE + 4];
    __shared__ float Bs[BK][TILE + 4];

    const int t = threadIdx.x;
    const int ty = t >> 4, tx = t & 15;        // 16x16 thread grid, 8x8 per thread
    const int i0 = bi * TILE, j0 = bj * TILE;
    const int lrow = t >> 1;                   // loader: row in tile
    const int lkq = (t & 1) * 4;               // loader: k quad
    const int lane = t & 31;

    unsigned long long acc[8][4];
    float cc[8][8];

    // ============ Phase A: label gram (K = 128) ============
    #pragma unroll
    for (int r = 0; r < 8; r++)
        #pragma unroll
        for (int c = 0; c < 4; c++) acc[r][c] = 0ull;

    {
        const float* Ab = labels + (size_t)i0 * CDIM;
        const float* Bb = labels + (size_t)j0 * CDIM;
        for (int kt = 0; kt < CDIM; kt += BK) {
            float4 va = *(const float4*)(Ab + lrow * CDIM + kt + lkq);
            float4 vb = *(const float4*)(Bb + lrow * CDIM + kt + lkq);
            __syncthreads();
            As[lkq + 0][lrow] = va.x; As[lkq + 1][lrow] = va.y;
            As[lkq + 2][lrow] = va.z; As[lkq + 3][lrow] = va.w;
            Bs[lkq + 0][lrow] = vb.x; Bs[lkq + 1][lrow] = vb.y;
            Bs[lkq + 2][lrow] = vb.z; Bs[lkq + 3][lrow] = vb.w;
            __syncthreads();
            #pragma unroll
            for (int k = 0; k < BK; k++) {
                float ar[8];
                *(float4*)(ar)     = *(const float4*)&As[k][ty * 8];
                *(float4*)(ar + 4) = *(const float4*)&As[k][ty * 8 + 4];
                ulonglong2 b01 = *(const ulonglong2*)&Bs[k][tx * 8];
                ulonglong2 b23 = *(const ulonglong2*)&Bs[k][tx * 8 + 4];
                unsigned long long bp[4] = {b01.x, b01.y, b23.x, b23.y};
                #pragma unroll
                for (int r = 0; r < 8; r++) {
                    unsigned long long ad = pack_dup(ar[r]);
                    #pragma unroll
                    for (int c = 0; c < 4; c++) acc[r][c] = ffma2(ad, bp[c], acc[r][c]);
                }
            }
        }
    }

    // epilogue A: normalize, store (both triangles), track min/max
    {
        float invi[8], invj[8];
        #pragma unroll
        for (int r = 0; r < 8; r++) invi[r] = g_invn[i0 + ty * 8 + r];
        #pragma unroll
        for (int c = 0; c < 8; c++) invj[c] = g_invn[j0 + tx * 8 + c];
        float lmin = 3.4e38f, lmax = -3.4e38f;
        #pragma unroll
        for (int r = 0; r < 8; r++)
            #pragma unroll
            for (int c = 0; c < 4; c++) {
                float2 v = unpack2(acc[r][c]);
                float s0 = v.x * invi[r] * invj[2 * c];
                float s1 = v.y * invi[r] * invj[2 * c + 1];
                cc[r][2 * c] = s0; cc[r][2 * c + 1] = s1;
                lmin = fminf(lmin, fminf(s0, s1));
                lmax = fmaxf(lmax, fmaxf(s0, s1));
            }
        #pragma unroll
        for (int r = 0; r < 8; r++) {
            size_t base = (size_t)(i0 + ty * 8 + r) * BSZ + j0 + tx * 8;
            *(float4*)&g_sim[base]     = make_float4(cc[r][0], cc[r][1], cc[r][2], cc[r][3]);
            *(float4*)&g_sim[base + 4] = make_float4(cc[r][4], cc[r][5], cc[r][6], cc[r][7]);
        }
        if (bj != bi) {   // mirrored store, packed along i so sectors stay full
            #pragma unroll
            for (int c = 0; c < 8; c++) {
                size_t base = (size_t)(j0 + tx * 8 + c) * BSZ + i0 + ty * 8;
                *(float4*)&g_sim[base]     = make_float4(cc[0][c], cc[1][c], cc[2][c], cc[3][c]);
                *(float4*)&g_sim[base + 4] = make_float4(cc[4][c], cc[5][c], cc[6][c], cc[7][c]);
            }
        }
        #pragma unroll
        for (int off = 16; off; off >>= 1) {
            lmin = fminf(lmin, __shfl_xor_sync(0xffffffffu, lmin, off));
            lmax = fmaxf(lmax, __shfl_xor_sync(0xffffffffu, lmax, off));
        }
        if (lane == 0) {
            atomicMin(&g_smin_enc, fenc(lmin));
            atomicMax(&g_smax_enc, fenc(lmax));
        }
    }

    // ============ Phase B: output gram -> distances (K = 256) ============
    #pragma unroll
    for (int r = 0; r < 8; r++)
        #pragma unroll
        for (int c = 0; c < 4; c++) acc[r][c] = 0ull;

    {
        const float* Ab = outputs + (size_t)i0 * DDIM;
        const float* Bb = outputs + (size_t)j0 * DDIM;
        for (int kt = 0; kt < DDIM; kt += BK) {
            float4 va = *(const float4*)(Ab + lrow * DDIM + kt + lkq);
            float4 vb = *(const float4*)(Bb + lrow * DDIM + kt + lkq);
            __syncthreads();
            As[lkq + 0][lrow] = va.x; As[lkq + 1][lrow] = va.y;
            As[lkq + 2][lrow] = va.z; As[lkq + 3][lrow] = va.w;
            Bs[lkq + 0][lrow] = vb.x; Bs[lkq + 1][lrow] = vb.y;
            Bs[lkq + 2][lrow] = vb.z; Bs[lkq + 3][lrow] = vb.w;
            __syncthreads();
            #pragma unroll
            for (int k = 0; k < BK; k++) {
                float ar[8];
                *(float4*)(ar)     = *(const float4*)&As[k][ty * 8];
                *(float4*)(ar + 4) = *(const float4*)&As[k][ty * 8 + 4];
                ulonglong2 b01 = *(const ulonglong2*)&Bs[k][tx * 8];
                ulonglong2 b23 = *(const ulonglong2*)&Bs[k][tx * 8 + 4];
                unsigned long long bp[4] = {b01.x, b01.y, b23.x, b23.y};
                #pragma unroll
                for (int r = 0; r < 8; r++) {
                    unsigned long long ad = pack_dup(ar[r]);
                    #pragma unroll
                    for (int c = 0; c < 4; c++) acc[r][c] = ffma2(ad, bp[c], acc[r][c]);
                }
            }
        }
    }

    // epilogue B: d2 = sq_i + sq_j - 2*dot, eud = d2>0 ? sqrt(d2) : 0
    {
        float sqi[8], sqj[8];
        #pragma unroll
        for (int r = 0; r < 8; r++) sqi[r] = g_sq[i0 + ty * 8 + r];
        #pragma unroll
        for (int c = 0; c < 8; c++) sqj[c] = g_sq[j0 + tx * 8 + c];
        float lemax = 0.0f;
        #pragma unroll
        for (int r = 0; r < 8; r++)
            #pragma unroll
            for (int c = 0; c < 4; c++) {
                float2 v = unpack2(acc[r][c]);
                float d0 = sqi[r] + sqj[2 * c] - 2.0f * v.x;
                float d1 = sqi[r] + sqj[2 * c + 1] - 2.0f * v.y;
                float e0 = (d0 > 0.0f) ? sqrtf(d0) : 0.0f;
                float e1 = (d1 > 0.0f) ? sqrtf(d1) : 0.0f;
                cc[r][2 * c] = e0; cc[r][2 * c + 1] = e1;
                lemax = fmaxf(lemax, fmaxf(e0, e1));
            }
        #pragma unroll
        for (int r = 0; r < 8; r++) {
            size_t base = (size_t)(i0 + ty * 8 + r) * BSZ + j0 + tx * 8;
            *(float4*)&g_eud[base]     = make_float4(cc[r][0], cc[r][1], cc[r][2], cc[r][3]);
            *(float4*)&g_eud[base + 4] = make_float4(cc[r][4], cc[r][5], cc[r][6], cc[r][7]);
        }
        if (bj != bi) {
            #pragma unroll
            for (int c = 0; c < 8; c++) {
                size_t base = (size_t)(j0 + tx * 8 + c) * BSZ + i0 + ty * 8;
                *(float4*)&g_eud[base]     = make_float4(cc[0][c], cc[1][c], cc[2][c], cc[3][c]);
                *(float4*)&g_eud[base + 4] = make_float4(cc[4][c], cc[5][c], cc[6][c], cc[7][c]);
            }
        }
        #pragma unroll
        for (int off = 16; off; off >>= 1)
            lemax = fmaxf(lemax, __shfl_xor_sync(0xffffffffu, lemax, off));
        if (lane == 0) atomicMax(&g_emax_enc, fenc(lemax));
    }
}

// ---------------- kernel 3: per-row masked log-sum-exp losses ----------------
__global__ __launch_bounds__(256) void loss_kernel() {
    const int row = blockIdx.x;
    const int t = threadIdx.x;
    const float smin = fdec(g_smin_enc);
    const float smax = fdec(g_smax_enc);
    const float emax = fdec(g_emax_enc);
    const float invr = 1.0f / (smax - smin);
    const float inve = 1.0f / emax;

    const float4* srow = (const float4*)(g_sim + (size_t)row * BSZ);
    const float4* erow = (const float4*)(g_eud + (size_t)row * BSZ);

    float p = 0.0f, n = 0.0f;
    for (int j = t; j < BSZ / 4; j += 256) {
        float4 s4 = srow[j];
        float4 e4 = erow[j];
        {
            float s = (s4.x - smin) * invr, d = e4.x * inve + s;
            if (s > 0.5f) p += __expf(d); else n += __expf(1.0f - d);
        }
        {
            float s = (s4.y - smin) * invr, d = e4.y * inve + s;
            if (s > 0.5f) p += __expf(d); else n += __expf(1.0f - d);
        }
        {
            float s = (s4.z - smin) * invr, d = e4.z * inve + s;
            if (s > 0.5f) p += __expf(d); else n += __expf(1.0f - d);
        }
        {
            float s = (s4.w - smin) * invr, d = e4.w * inve + s;
            if (s > 0.5f) p += __expf(d); else n += __expf(1.0f - d);
        }
    }
    #pragma unroll
    for (int off = 16; off; off >>= 1) {
        p += __shfl_xor_sync(0xffffffffu, p, off);
        n += __shfl_xor_sync(0xffffffffu, n, off);
    }
    __shared__ float sp[8], sn[8];
    if ((t & 31) == 0) { sp[t >> 5] = p; sn[t >> 5] = n; }
    __syncthreads();
    if (t == 0) {
        float P = 0.0f, N = 0.0f;
        #pragma unroll
        for (int w = 0; w < 8; w++) { P += sp[w]; N += sn[w]; }
        float lp = fmaxf(logf(P), 0.0f);   // log(0) = -inf -> clamped to 0
        float ln = fmaxf(logf(N), 0.0f);
        g_rowloss[row] = lp + ln;
    }
}

// ---------------- kernel 4: deterministic final mean ----------------
__global__ __launch_bounds__(256) void final_kernel(float* __restrict__ out) {
    __shared__ float s[256];
    const int t = threadIdx.x;
    float a = 0.0f;
    for (int i = t; i < BSZ; i += 256) a += g_rowloss[i];
    s[t] = a;
    __syncthreads();
    #pragma unroll
    for (int o = 128; o; o >>= 1) {
        if (t < o) s[t] += s[t + o];
        __syncthreads();
    }
    if (t == 0) out[0] = s[0] * (1.0f / (float)BSZ);
}

// ---------------- launch ----------------
extern "C" void kernel_launch(void* const* d_in, const int* in_sizes, int n_in,
                              void* d_out, int out_size) {
    const float* outputs = (const float*)d_in[0];
    const float* labels  = (const float*)d_in[1];
    // robustness: identify by element count (outputs = B*D, labels = B*C)
    if (n_in >= 2 && in_sizes[0] == BSZ * CDIM && in_sizes[1] == BSZ * DDIM) {
        const float* tmp = outputs; outputs = labels; labels = tmp;
    }
    float* out = (float*)d_out;

    init_kernel<<<1, 1>>>();
    rownorm_kernel<<<BSZ, 256>>>(outputs, labels);
    gram_kernel<<<dim3(64, 64), 256>>>(outputs, labels);
    loss_kernel<<<BSZ, 256>>>();
    final_kernel<<<1, 256>>>(out);
}

// round 3
// speedup vs baseline: 1.8196x; 1.8196x over previous
#include <cuda_runtime.h>
#include <cstdint>

#define BSZ 8192
#define CDIM 128
#define DDIM 256
#define TILE 128

// ---------------- scratch (static device globals; no allocation) ----------------
__device__ float g_sim[(size_t)BSZ * BSZ];   // raw cosine-sim gram (256 MB)
__device__ float g_eud[(size_t)BSZ * BSZ];   // raw euclidean distances (256 MB)
__device__ float g_invn[BSZ];                // 1/(||label_i|| + 1e-12)
__device__ float g_sq[BSZ];                  // ||output_i||^2
__device__ float g_rowloss[BSZ];
__device__ unsigned g_smin_enc, g_smax_enc, g_emax_enc;

// monotone float <-> uint encoding so min/max reduce with integer atomics
__device__ __forceinline__ unsigned fenc(float f) {
    unsigned u = __float_as_uint(f);
    return (u & 0x80000000u) ? ~u : (u | 0x80000000u);
}
__device__ __forceinline__ float fdec(unsigned e) {
    unsigned u = (e & 0x80000000u) ? (e & 0x7FFFFFFFu) : ~e;
    return __uint_as_float(u);
}

// tf32 round (rna) — keeps value as float bit-pattern for smem staging
__device__ __forceinline__ float tf32f(float f) {
    uint32_t u;
    asm("cvt.rna.tf32.f32 %0, %1;" : "=r"(u) : "f"(f));
    return __uint_as_float(u);
}

// legacy tensor-core MMA (sm_80+ baseline PTX -> HMMA on sm_103)
__device__ __forceinline__ void mma_tf32(float* c, uint4 a, uint2 b) {
    asm volatile(
        "mma.sync.aligned.m16n8k8.row.col.f32.tf32.tf32.f32 "
        "{%0,%1,%2,%3}, {%4,%5,%6,%7}, {%8,%9}, {%0,%1,%2,%3};"
        : "+f"(c[0]), "+f"(c[1]), "+f"(c[2]), "+f"(c[3])
        : "r"(a.x), "r"(a.y), "r"(a.z), "r"(a.w), "r"(b.x), "r"(b.y));
}

// ---------------- smem layout (floats) ----------------
// apack: 2 bufs x 4096 f  = [buf][ks(4)][mf(8)][lane(32)][reg(4)]
// bpack: 2 bufs x 4096 f  = [buf][ks(4)][nf(16)][lane(32)][reg(2)]
// smT  : 16384 f (reuses apack+bpack region for mirror transpose)
#define OFF_BPACK 8192
#define OFF_INVJ  16384
#define OFF_SQJ   16512
#define OFF_INVI  16640
#define OFF_SQI   16768
#define SM_FLOATS 16896
#define SM_BYTES  (SM_FLOATS * 4)

// fragment-packed loaders: read 128 rows x 32 k of X, tf32-convert, scatter
__device__ __forceinline__ void load_A(const float* __restrict__ X, int ld, int k0,
                                       float* __restrict__ ap, int tid) {
    #pragma unroll
    for (int it = 0; it < 4; it++) {
        int e = tid + 256 * it;                 // 0..1023
        int m = e >> 3, q = e & 7;              // m row, q = k-quad (4 floats)
        float4 v = *(const float4*)(X + (size_t)m * ld + k0 + q * 4);
        int ks = q >> 1, khi = q & 1;
        int mf = m >> 4, g = m & 7, hi = (m >> 3) & 1;
        float* base = ap + (size_t)((ks * 8 + mf) * 32 + g * 4) * 4 + (hi + 2 * khi);
        base[0]  = tf32f(v.x);                  // tig = 0..3 -> lane +1 -> +4 floats
        base[4]  = tf32f(v.y);
        base[8]  = tf32f(v.z);
        base[12] = tf32f(v.w);
    }
}
__device__ __forceinline__ void load_B(const float* __restrict__ X, int ld, int k0,
                                       float* __restrict__ bp, int tid) {
    #pragma unroll
    for (int it = 0; it < 4; it++) {
        int e = tid + 256 * it;
        int n = e >> 3, q = e & 7;
        float4 v = *(const float4*)(X + (size_t)n * ld + k0 + q * 4);
        int ks = q >> 1, khi = q & 1;
        int nf = n >> 3, g = n & 7;
        float* base = bp + (size_t)((ks * 16 + nf) * 32 + g * 4) * 2 + khi;
        base[0] = tf32f(v.x);
        base[2] = tf32f(v.y);
        base[4] = tf32f(v.z);
        base[6] = tf32f(v.w);
    }
}

// ---------------- kernel 0: reset global reduction scalars ----------------
__global__ void init_kernel() {
    g_smin_enc = fenc(3.4e38f);
    g_smax_enc = fenc(-3.4e38f);
    g_emax_enc = fenc(0.0f);
}

// ---------------- kernel 1: per-row norms ----------------
__global__ __launch_bounds__(256) void rownorm_kernel(const float* __restrict__ outputs,
                                                      const float* __restrict__ labels) {
    const int row = blockIdx.x;
    const int t = threadIdx.x;
    float l = (t < CDIM) ? labels[(size_t)row * CDIM + t] : 0.0f;
    float lsum = l * l;
    float o = outputs[(size_t)row * DDIM + t];
    float osum = o * o;
    #pragma unroll
    for (int off = 16; off; off >>= 1) {
        lsum += __shfl_xor_sync(0xffffffffu, lsum, off);
        osum += __shfl_xor_sync(0xffffffffu, osum, off);
    }
    __shared__ float sl[8], so[8];
    if ((t & 31) == 0) { sl[t >> 5] = lsum; so[t >> 5] = osum; }
    __syncthreads();
    if (t == 0) {
        float L = 0.0f, O = 0.0f;
        #pragma unroll
        for (int w = 0; w < 8; w++) { L += sl[w]; O += so[w]; }
        g_invn[row] = 1.0f / (sqrtf(L) + 1e-12f);
        g_sq[row] = O;
    }
}

// ---------------- kernel 2: mma.sync tf32 fused upper-triangle grams ----------------
__global__ __launch_bounds__(256, 2) void gram_mma(const float* __restrict__ outputs,
                                                   const float* __restrict__ labels) {
    const int bi = blockIdx.y, bj = blockIdx.x;
    if (bj < bi) return;
    extern __shared__ float sm[];
    float* apack = sm;
    float* bpack = sm + OFF_BPACK;
    float* smT   = sm;                    // reused for mirror transpose
    float* s_invj = sm + OFF_INVJ;
    float* s_sqj  = sm + OFF_SQJ;
    float* s_invi = sm + OFF_INVI;
    float* s_sqi  = sm + OFF_SQI;

    const int tid = threadIdx.x;
    const int wid = tid >> 5, lane = tid & 31;
    const int warp_m = wid >> 2, warp_n = wid & 3;
    const int g = lane >> 2, tig = lane & 3;
    const int i0 = bi * TILE, j0 = bj * TILE;
    const bool mirror = (bi != bj);

    if (tid < 128) {
        s_invj[tid] = g_invn[j0 + tid];
        s_sqj[tid]  = g_sq[j0 + tid];
        s_invi[tid] = g_invn[i0 + tid];
        s_sqi[tid]  = g_sq[i0 + tid];
    }

    float c[4][4][4];

    // =========================== Phase A: label gram (K=128) ===========================
    #pragma unroll
    for (int mf = 0; mf < 4; mf++)
        #pragma unroll
        for (int nf = 0; nf < 4; nf++)
            #pragma unroll
            for (int r = 0; r < 4; r++) c[mf][nf][r] = 0.0f;

    {
        const float* Ai = labels + (size_t)i0 * CDIM;
        const float* Bj = labels + (size_t)j0 * CDIM;
        load_A(Ai, CDIM, 0, apack, tid);
        load_B(Bj, CDIM, 0, bpack, tid);
        __syncthreads();
        for (int ch = 0; ch < 4; ch++) {
            if (ch < 3) {
                load_A(Ai, CDIM, (ch + 1) * 32, apack + ((ch + 1) & 1) * 4096, tid);
                load_B(Bj, CDIM, (ch + 1) * 32, bpack + ((ch + 1) & 1) * 4096, tid);
            }
            const float* ap = apack + (ch & 1) * 4096;
            const float* bp = bpack + (ch & 1) * 4096;
            #pragma unroll
            for (int ks = 0; ks < 4; ks++) {
                uint4 a[4]; uint2 b[4];
                #pragma unroll
                for (int mf = 0; mf < 4; mf++)
                    a[mf] = *(const uint4*)(ap + (size_t)((ks * 8 + warp_m * 4 + mf) * 32 + lane) * 4);
                #pragma unroll
                for (int nf = 0; nf < 4; nf++)
                    b[nf] = *(const uint2*)(bp + (size_t)((ks * 16 + warp_n * 4 + nf) * 32 + lane) * 2);
                #pragma unroll
                for (int mf = 0; mf < 4; mf++)
                    #pragma unroll
                    for (int nf = 0; nf < 4; nf++)
                        mma_tf32(c[mf][nf], a[mf], b[nf]);
            }
            __syncthreads();
        }
    }

    // epilogue A: sim; direct store + swizzled smem transpose for mirror; min/max
    {
        float lmin = 3.4e38f, lmax = -3.4e38f;
        #pragma unroll
        for (int mf = 0; mf < 4; mf++) {
            int il = warp_m * 64 + mf * 16 + g;
            float vi0 = s_invi[il], vi1 = s_invi[il + 8];
            #pragma unroll
            for (int nf = 0; nf < 4; nf++) {
                int jl = warp_n * 32 + nf * 8 + 2 * tig;
                float vj0 = s_invj[jl], vj1 = s_invj[jl + 1];
                float v0 = c[mf][nf][0] * vi0 * vj0;
                float v1 = c[mf][nf][1] * vi0 * vj1;
                float v2 = c[mf][nf][2] * vi1 * vj0;
                float v3 = c[mf][nf][3] * vi1 * vj1;
                lmin = fminf(lmin, fminf(fminf(v0, v1), fminf(v2, v3)));
                lmax = fmaxf(lmax, fmaxf(fmaxf(v0, v1), fmaxf(v2, v3)));
                *(float2*)&g_sim[(size_t)(i0 + il) * BSZ + j0 + jl]     = make_float2(v0, v1);
                *(float2*)&g_sim[(size_t)(i0 + il + 8) * BSZ + j0 + jl] = make_float2(v2, v3);
                if (mirror) {
                    int f0 = (jl & 6) << 2, f1 = ((jl + 1) & 6) << 2;
                    smT[jl * 128 + (il ^ f0)]             = v0;
                    smT[(jl + 1) * 128 + (il ^ f1)]       = v1;
                    smT[jl * 128 + ((il + 8) ^ f0)]       = v2;
                    smT[(jl + 1) * 128 + ((il + 8) ^ f1)] = v3;
                }
            }
        }
        if (mirror) {
            __syncthreads();
            #pragma unroll
            for (int r = 0; r < 16; r++) {
                int row = wid * 16 + r;
                int cl = lane * 4;
                float4 v = *(const float4*)&smT[row * 128 + (cl ^ ((row & 6) << 2))];
                *(float4*)&g_sim[(size_t)(j0 + row) * BSZ + i0 + cl] = v;
            }
        }
        __syncthreads();
        #pragma unroll
        for (int off = 16; off; off >>= 1) {
            lmin = fminf(lmin, __shfl_xor_sync(0xffffffffu, lmin, off));
            lmax = fmaxf(lmax, __shfl_xor_sync(0xffffffffu, lmax, off));
        }
        if (lane == 0) {
            atomicMin(&g_smin_enc, fenc(lmin));
            atomicMax(&g_smax_enc, fenc(lmax));
        }
    }

    // =========================== Phase B: output gram (K=256) ===========================
    #pragma unroll
    for (int mf = 0; mf < 4; mf++)
        #pragma unroll
        for (int nf = 0; nf < 4; nf++)
            #pragma unroll
            for (int r = 0; r < 4; r++) c[mf][nf][r] = 0.0f;

    {
        const float* Ai = outputs + (size_t)i0 * DDIM;
        const float* Bj = outputs + (size_t)j0 * DDIM;
        load_A(Ai, DDIM, 0, apack, tid);
        load_B(Bj, DDIM, 0, bpack, tid);
        __syncthreads();
        for (int ch = 0; ch < 8; ch++) {
            if (ch < 7) {
                load_A(Ai, DDIM, (ch + 1) * 32, apack + ((ch + 1) & 1) * 4096, tid);
                load_B(Bj, DDIM, (ch + 1) * 32, bpack + ((ch + 1) & 1) * 4096, tid);
            }
            const float* ap = apack + (ch & 1) * 4096;
            const float* bp = bpack + (ch & 1) * 4096;
            #pragma unroll
            for (int ks = 0; ks < 4; ks++) {
                uint4 a[4]; uint2 b[4];
                #pragma unroll
                for (int mf = 0; mf < 4; mf++)
                    a[mf] = *(const uint4*)(ap + (size_t)((ks * 8 + warp_m * 4 + mf) * 32 + lane) * 4);
                #pragma unroll
                for (int nf = 0; nf < 4; nf++)
                    b[nf] = *(const uint2*)(bp + (size_t)((ks * 16 + warp_n * 4 + nf) * 32 + lane) * 2);
                #pragma unroll
                for (int mf = 0; mf < 4; mf++)
                    #pragma unroll
                    for (int nf = 0; nf < 4; nf++)
                        mma_tf32(c[mf][nf], a[mf], b[nf]);
            }
            __syncthreads();
        }
    }

    // epilogue B: d2 = sq_i + sq_j - 2*dot; eud = d2>0 ? sqrt : 0 (diag forced 0)
    {
        float lemax = 0.0f;
        #pragma unroll
        for (int mf = 0; mf < 4; mf++) {
            int il = warp_m * 64 + mf * 16 + g;
            float q0 = s_sqi[il], q1 = s_sqi[il + 8];
            #pragma unroll
            for (int nf = 0; nf < 4; nf++) {
                int jl = warp_n * 32 + nf * 8 + 2 * tig;
                float r0 = s_sqj[jl], r1 = s_sqj[jl + 1];
                float d0 = q0 + r0 - 2.0f * c[mf][nf][0];
                float d1 = q0 + r1 - 2.0f * c[mf][nf][1];
                float d2_ = q1 + r0 - 2.0f * c[mf][nf][2];
                float d3 = q1 + r1 - 2.0f * c[mf][nf][3];
                float v0 = (d0 > 0.0f) ? sqrtf(d0) : 0.0f;
                float v1 = (d1 > 0.0f) ? sqrtf(d1) : 0.0f;
                float v2 = (d2_ > 0.0f) ? sqrtf(d2_) : 0.0f;
                float v3 = (d3 > 0.0f) ? sqrtf(d3) : 0.0f;
                if (i0 + il == j0 + jl) v0 = 0.0f;
                if (i0 + il == j0 + jl + 1) v1 = 0.0f;
                if (i0 + il + 8 == j0 + jl) v2 = 0.0f;
                if (i0 + il + 8 == j0 + jl + 1) v3 = 0.0f;
                lemax = fmaxf(lemax, fmaxf(fmaxf(v0, v1), fmaxf(v2, v3)));
                *(float2*)&g_eud[(size_t)(i0 + il) * BSZ + j0 + jl]     = make_float2(v0, v1);
                *(float2*)&g_eud[(size_t)(i0 + il + 8) * BSZ + j0 + jl] = make_float2(v2, v3);
                if (mirror) {
                    int f0 = (jl & 6) << 2, f1 = ((jl + 1) & 6) << 2;
                    smT[jl * 128 + (il ^ f0)]             = v0;
                    smT[(jl + 1) * 128 + (il ^ f1)]       = v1;
                    smT[jl * 128 + ((il + 8) ^ f0)]       = v2;
                    smT[(jl + 1) * 128 + ((il + 8) ^ f1)] = v3;
                }
            }
        }
        if (mirror) {
            __syncthreads();
            #pragma unroll
            for (int r = 0; r < 16; r++) {
                int row = wid * 16 + r;
                int cl = lane * 4;
                float4 v = *(const float4*)&smT[row * 128 + (cl ^ ((row & 6) << 2))];
                *(float4*)&g_eud[(size_t)(j0 + row) * BSZ + i0 + cl] = v;
            }
        }
        #pragma unroll
        for (int off = 16; off; off >>= 1)
            lemax = fmaxf(lemax, __shfl_xor_sync(0xffffffffu, lemax, off));
        if (lane == 0) atomicMax(&g_emax_enc, fenc(lemax));
    }
}

// ---------------- kernel 3: per-row masked log-sum-exp losses ----------------
__global__ __launch_bounds__(256) void loss_kernel() {
    const int row = blockIdx.x;
    const int t = threadIdx.x;
    const float smin = fdec(g_smin_enc);
    const float smax = fdec(g_smax_enc);
    const float emax = fdec(g_emax_enc);
    const float invr = 1.0f / (smax - smin);
    const float inve = 1.0f / emax;

    const float4* srow = (const float4*)(g_sim + (size_t)row * BSZ);
    const float4* erow = (const float4*)(g_eud + (size_t)row * BSZ);

    float p = 0.0f, n = 0.0f;
    for (int j = t; j < BSZ / 4; j += 256) {
        float4 s4 = srow[j];
        float4 e4 = erow[j];
        {
            float s = (s4.x - smin) * invr, d = e4.x * inve + s;
            if (s > 0.5f) p += __expf(d); else n += __expf(1.0f - d);
        }
        {
            float s = (s4.y - smin) * invr, d = e4.y * inve + s;
            if (s > 0.5f) p += __expf(d); else n += __expf(1.0f - d);
        }
        {
            float s = (s4.z - smin) * invr, d = e4.z * inve + s;
            if (s > 0.5f) p += __expf(d); else n += __expf(1.0f - d);
        }
        {
            float s = (s4.w - smin) * invr, d = e4.w * inve + s;
            if (s > 0.5f) p += __expf(d); else n += __expf(1.0f - d);
        }
    }
    #pragma unroll
    for (int off = 16; off; off >>= 1) {
        p += __shfl_xor_sync(0xffffffffu, p, off);
        n += __shfl_xor_sync(0xffffffffu, n, off);
    }
    __shared__ float sp[8], sn[8];
    if ((t & 31) == 0) { sp[t >> 5] = p; sn[t >> 5] = n; }
    __syncthreads();
    if (t == 0) {
        float P = 0.0f, N = 0.0f;
        #pragma unroll
        for (int w = 0; w < 8; w++) { P += sp[w]; N += sn[w]; }
        float lp = fmaxf(logf(P), 0.0f);
        float ln = fmaxf(logf(N), 0.0f);
        g_rowloss[row] = lp + ln;
    }
}

// ---------------- kernel 4: deterministic final mean ----------------
__global__ __launch_bounds__(256) void final_kernel(float* __restrict__ out) {
    __shared__ float s[256];
    const int t = threadIdx.x;
    float a = 0.0f;
    for (int i = t; i < BSZ; i += 256) a += g_rowloss[i];
    s[t] = a;
    __syncthreads();
    #pragma unroll
    for (int o = 128; o; o >>= 1) {
        if (t < o) s[t] += s[t + o];
        __syncthreads();
    }
    if (t == 0) out[0] = s[0] * (1.0f / (float)BSZ);
}

// ---------------- launch ----------------
extern "C" void kernel_launch(void* const* d_in, const int* in_sizes, int n_in,
                              void* d_out, int out_size) {
    const float* outputs = (const float*)d_in[0];
    const float* labels  = (const float*)d_in[1];
    if (n_in >= 2 && in_sizes[0] == BSZ * CDIM && in_sizes[1] == BSZ * DDIM) {
        const float* tmp = outputs; outputs = labels; labels = tmp;
    }
    float* out = (float*)d_out;

    static bool attr_done = false;
    if (!attr_done) {
        cudaFuncSetAttribute(gram_mma, cudaFuncAttributeMaxDynamicSharedMemorySize, SM_BYTES);
        attr_done = true;
    }

    init_kernel<<<1, 1>>>();
    rownorm_kernel<<<BSZ, 256>>>(outputs, labels);
    gram_mma<<<dim3(64, 64), 256, SM_BYTES>>>(outputs, labels);
    loss_kernel<<<BSZ, 256>>>();
    final_kernel<<<1, 256>>>(out);
}

// round 4
// speedup vs baseline: 2.5997x; 1.4287x over previous
#include <cuda_runtime.h>
#include <cuda_fp16.h>
#include <cstdint>

#define BSZ 8192
#define CDIM 128
#define DDIM 256
#define TILE 128

// ---------------- scratch (static device globals; no allocation) ----------------
__device__ __half g_sim[(size_t)BSZ * BSZ];  // raw cosine-sim gram (128 MB, fp16)
__device__ __half g_eud[(size_t)BSZ * BSZ];  // raw euclidean distances (128 MB, fp16)
__device__ float g_invn[BSZ];                // 1/(||label_i|| + 1e-12)
__device__ float g_sq[BSZ];                  // ||output_i||^2
__device__ float g_rowloss[BSZ];
__device__ unsigned g_smin_enc, g_smax_enc, g_emax_enc;

// monotone float <-> uint encoding so min/max reduce with integer atomics
__device__ __forceinline__ unsigned fenc(float f) {
    unsigned u = __float_as_uint(f);
    return (u & 0x80000000u) ? ~u : (u | 0x80000000u);
}
__device__ __forceinline__ float fdec(unsigned e) {
    unsigned u = (e & 0x80000000u) ? (e & 0x7FFFFFFFu) : ~e;
    return __uint_as_float(u);
}

// tf32 round (rna) — keeps value as float bit-pattern for smem staging
__device__ __forceinline__ float tf32f(float f) {
    uint32_t u;
    asm("cvt.rna.tf32.f32 %0, %1;" : "=r"(u) : "f"(f));
    return __uint_as_float(u);
}

// legacy tensor-core MMA (sm_80+ baseline PTX -> HMMA on sm_103)
__device__ __forceinline__ void mma_tf32(float* c, uint4 a, uint2 b) {
    asm volatile(
        "mma.sync.aligned.m16n8k8.row.col.f32.tf32.tf32.f32 "
        "{%0,%1,%2,%3}, {%4,%5,%6,%7}, {%8,%9}, {%0,%1,%2,%3};"
        : "+f"(c[0]), "+f"(c[1]), "+f"(c[2]), "+f"(c[3])
        : "r"(a.x), "r"(a.y), "r"(a.z), "r"(a.w), "r"(b.x), "r"(b.y));
}

// ---------------- smem layout (floats) ----------------
// apack: 2 bufs x 4096 f  = [buf][ks(4)][mf(8)][reg(4)][fraglane(32)], g-swizzled
// bpack: 2 bufs x 4096 f  = [buf][ks(4)][nf(16)][reg(2)][fraglane(32)], g-swizzled
// smT  : 16384 f (reuses apack+bpack region for mirror transpose)
#define OFF_BPACK 8192
#define OFF_INVJ  16384
#define OFF_SQJ   16512
#define OFF_INVI  16640
#define OFF_SQI   16768
#define SM_FLOATS 16896
#define SM_BYTES  (SM_FLOATS * 4)

// fragment-packed loaders: read 128 rows x 32 k of X, tf32-convert, STS.128
// apack word = ((ks*8+mf)*4 + reg)*32 + ((g ^ (2ks+khi))*4 + tig)
__device__ __forceinline__ void load_A(const float* __restrict__ X, int ld, int k0,
                                       float* __restrict__ ap, int tid) {
    #pragma unroll
    for (int it = 0; it < 4; it++) {
        int e = tid + 256 * it;                 // 0..1023
        int m = e >> 3, q = e & 7;              // q = 2*ks + khi
        float4 v = *(const float4*)(X + (size_t)m * ld + k0 + q * 4);
        int ks = q >> 1, khi = q & 1;
        int mf = m >> 4, g = m & 7, hi = (m >> 3) & 1;
        int reg = hi + 2 * khi;
        int word = (((ks * 8 + mf) * 4 + reg) << 5) + ((g ^ q) << 2);
        float4 t = make_float4(tf32f(v.x), tf32f(v.y), tf32f(v.z), tf32f(v.w));
        *(float4*)(ap + word) = t;
    }
}
// bpack word = ((ks*16+nf)*2 + khi)*32 + ((gn ^ (2ks+khi))*4 + tig)
__device__ __forceinline__ void load_B(const float* __restrict__ X, int ld, int k0,
                                       float* __restrict__ bp, int tid) {
    #pragma unroll
    for (int it = 0; it < 4; it++) {
        int e = tid + 256 * it;
        int n = e >> 3, q = e & 7;
        float4 v = *(const float4*)(X + (size_t)n * ld + k0 + q * 4);
        int ks = q >> 1, khi = q & 1;
        int nf = n >> 3, gn = n & 7;
        int word = (((ks * 16 + nf) * 2 + khi) << 5) + ((gn ^ q) << 2);
        float4 t = make_float4(tf32f(v.x), tf32f(v.y), tf32f(v.z), tf32f(v.w));
        *(float4*)(bp + word) = t;
    }
}

// ---------------- kernel 0: reset global reduction scalars ----------------
__global__ void init_kernel() {
    g_smin_enc = fenc(3.4e38f);
    g_smax_enc = fenc(-3.4e38f);
    g_emax_enc = fenc(0.0f);
}

// ---------------- kernel 1: per-row norms ----------------
__global__ __launch_bounds__(256) void rownorm_kernel(const float* __restrict__ outputs,
                                                      const float* __restrict__ labels) {
    const int row = blockIdx.x;
    const int t = threadIdx.x;
    float l = (t < CDIM) ? labels[(size_t)row * CDIM + t] : 0.0f;
    float lsum = l * l;
    float o = outputs[(size_t)row * DDIM + t];
    float osum = o * o;
    #pragma unroll
    for (int off = 16; off; off >>= 1) {
        lsum += __shfl_xor_sync(0xffffffffu, lsum, off);
        osum += __shfl_xor_sync(0xffffffffu, osum, off);
    }
    __shared__ float sl[8], so[8];
    if ((t & 31) == 0) { sl[t >> 5] = lsum; so[t >> 5] = osum; }
    __syncthreads();
    if (t == 0) {
        float L = 0.0f, O = 0.0f;
        #pragma unroll
        for (int w = 0; w < 8; w++) { L += sl[w]; O += so[w]; }
        g_invn[row] = 1.0f / (sqrtf(L) + 1e-12f);
        g_sq[row] = O;
    }
}

// fragment readers (swizzle-aware, conflict-free LDS.32)
__device__ __forceinline__ uint4 read_afrag(const float* __restrict__ ap,
                                            int ks, int mfabs, int offk0, int offk1) {
    const float* p = ap + (((ks * 8 + mfabs) * 4) << 5);
    uint4 a;
    a.x = __float_as_uint(p[offk0]);
    a.y = __float_as_uint(p[32 + offk0]);
    a.z = __float_as_uint(p[64 + offk1]);
    a.w = __float_as_uint(p[96 + offk1]);
    return a;
}
__device__ __forceinline__ uint2 read_bfrag(const float* __restrict__ bp,
                                            int ks, int nfabs, int offk0, int offk1) {
    const float* p = bp + (((ks * 16 + nfabs) * 2) << 5);
    uint2 b;
    b.x = __float_as_uint(p[offk0]);
    b.y = __float_as_uint(p[32 + offk1]);
    return b;
}

// ---------------- kernel 2: mma.sync tf32 fused upper-triangle grams ----------------
__global__ __launch_bounds__(256, 2) void gram_mma(const float* __restrict__ outputs,
                                                   const float* __restrict__ labels) {
    const int bi = blockIdx.y, bj = blockIdx.x;
    if (bj < bi) return;
    extern __shared__ float sm[];
    float* apack = sm;
    float* bpack = sm + OFF_BPACK;
    float* smT   = sm;                    // reused for mirror transpose
    float* s_invj = sm + OFF_INVJ;
    float* s_sqj  = sm + OFF_SQJ;
    float* s_invi = sm + OFF_INVI;
    float* s_sqi  = sm + OFF_SQI;

    const int tid = threadIdx.x;
    const int wid = tid >> 5, lane = tid & 31;
    const int warp_m = wid >> 2, warp_n = wid & 3;
    const int g = lane >> 2, tig = lane & 3;
    const int i0 = bi * TILE, j0 = bj * TILE;
    const bool mirror = (bi != bj);

    if (tid < 128) {
        s_invj[tid] = g_invn[j0 + tid];
        s_sqj[tid]  = g_sq[j0 + tid];
        s_invi[tid] = g_invn[i0 + tid];
        s_sqi[tid]  = g_sq[i0 + tid];
    }

    float c[4][4][4];

    // =========================== Phase A: label gram (K=128) ===========================
    #pragma unroll
    for (int mf = 0; mf < 4; mf++)
        #pragma unroll
        for (int nf = 0; nf < 4; nf++)
            #pragma unroll
            for (int r = 0; r < 4; r++) c[mf][nf][r] = 0.0f;

    {
        const float* Ai = labels + (size_t)i0 * CDIM;
        const float* Bj = labels + (size_t)j0 * CDIM;
        load_A(Ai, CDIM, 0, apack, tid);
        load_B(Bj, CDIM, 0, bpack, tid);
        __syncthreads();
        for (int ch = 0; ch < 4; ch++) {
            if (ch < 3) {
                load_A(Ai, CDIM, (ch + 1) * 32, apack + ((ch + 1) & 1) * 4096, tid);
                load_B(Bj, CDIM, (ch + 1) * 32, bpack + ((ch + 1) & 1) * 4096, tid);
            }
            const float* ap = apack + (ch & 1) * 4096;
            const float* bp = bpack + (ch & 1) * 4096;
            #pragma unroll
            for (int ks = 0; ks < 4; ks++) {
                const int offk0 = ((g ^ (2 * ks)) << 2) + tig;
                const int offk1 = ((g ^ (2 * ks + 1)) << 2) + tig;
                uint4 a[4]; uint2 b[4];
                #pragma unroll
                for (int mf = 0; mf < 4; mf++)
                    a[mf] = read_afrag(ap, ks, warp_m * 4 + mf, offk0, offk1);
                #pragma unroll
                for (int nf = 0; nf < 4; nf++)
                    b[nf] = read_bfrag(bp, ks, warp_n * 4 + nf, offk0, offk1);
                #pragma unroll
                for (int mf = 0; mf < 4; mf++)
                    #pragma unroll
                    for (int nf = 0; nf < 4; nf++)
                        mma_tf32(c[mf][nf], a[mf], b[nf]);
            }
            __syncthreads();
        }
    }

    // epilogue A: sim; fp16 direct store + swizzled smem transpose for mirror; min/max
    {
        float lmin = 3.4e38f, lmax = -3.4e38f;
        #pragma unroll
        for (int mf = 0; mf < 4; mf++) {
            int il = warp_m * 64 + mf * 16 + g;
            float vi0 = s_invi[il], vi1 = s_invi[il + 8];
            #pragma unroll
            for (int nf = 0; nf < 4; nf++) {
                int jl = warp_n * 32 + nf * 8 + 2 * tig;
                float vj0 = s_invj[jl], vj1 = s_invj[jl + 1];
                float v0 = c[mf][nf][0] * vi0 * vj0;
                float v1 = c[mf][nf][1] * vi0 * vj1;
                float v2 = c[mf][nf][2] * vi1 * vj0;
                float v3 = c[mf][nf][3] * vi1 * vj1;
                lmin = fminf(lmin, fminf(fminf(v0, v1), fminf(v2, v3)));
                lmax = fmaxf(lmax, fmaxf(fmaxf(v0, v1), fmaxf(v2, v3)));
                *(__half2*)&g_sim[(size_t)(i0 + il) * BSZ + j0 + jl]     = __floats2half2_rn(v0, v1);
                *(__half2*)&g_sim[(size_t)(i0 + il + 8) * BSZ + j0 + jl] = __floats2half2_rn(v2, v3);
                if (mirror) {
                    int f0 = (jl & 6) << 2, f1 = ((jl + 1) & 6) << 2;
                    smT[jl * 128 + (il ^ f0)]             = v0;
                    smT[(jl + 1) * 128 + (il ^ f1)]       = v1;
                    smT[jl * 128 + ((il + 8) ^ f0)]       = v2;
                    smT[(jl + 1) * 128 + ((il + 8) ^ f1)] = v3;
                }
            }
        }
        if (mirror) {
            __syncthreads();
            #pragma unroll
            for (int r = 0; r < 16; r++) {
                int row = wid * 16 + r;
                int cl = lane * 4;
                float4 v = *(const float4*)&smT[row * 128 + (cl ^ ((row & 6) << 2))];
                __half2 h01 = __floats2half2_rn(v.x, v.y);
                __half2 h23 = __floats2half2_rn(v.z, v.w);
                uint2 u = make_uint2(*(unsigned*)&h01, *(unsigned*)&h23);
                *(uint2*)&g_sim[(size_t)(j0 + row) * BSZ + i0 + cl] = u;
            }
        }
        __syncthreads();
        #pragma unroll
        for (int off = 16; off; off >>= 1) {
            lmin = fminf(lmin, __shfl_xor_sync(0xffffffffu, lmin, off));
            lmax = fmaxf(lmax, __shfl_xor_sync(0xffffffffu, lmax, off));
        }
        if (lane == 0) {
            atomicMin(&g_smin_enc, fenc(lmin));
            atomicMax(&g_smax_enc, fenc(lmax));
        }
    }

    // =========================== Phase B: output gram (K=256) ===========================
    #pragma unroll
    for (int mf = 0; mf < 4; mf++)
        #pragma unroll
        for (int nf = 0; nf < 4; nf++)
            #pragma unroll
            for (int r = 0; r < 4; r++) c[mf][nf][r] = 0.0f;

    {
        const float* Ai = outputs + (size_t)i0 * DDIM;
        const float* Bj = outputs + (size_t)j0 * DDIM;
        load_A(Ai, DDIM, 0, apack, tid);
        load_B(Bj, DDIM, 0, bpack, tid);
        __syncthreads();
        for (int ch = 0; ch < 8; ch++) {
            if (ch < 7) {
                load_A(Ai, DDIM, (ch + 1) * 32, apack + ((ch + 1) & 1) * 4096, tid);
                load_B(Bj, DDIM, (ch + 1) * 32, bpack + ((ch + 1) & 1) * 4096, tid);
            }
            const float* ap = apack + (ch & 1) * 4096;
            const float* bp = bpack + (ch & 1) * 4096;
            #pragma unroll
            for (int ks = 0; ks < 4; ks++) {
                const int offk0 = ((g ^ (2 * ks)) << 2) + tig;
                const int offk1 = ((g ^ (2 * ks + 1)) << 2) + tig;
                uint4 a[4]; uint2 b[4];
                #pragma unroll
                for (int mf = 0; mf < 4; mf++)
                    a[mf] = read_afrag(ap, ks, warp_m * 4 + mf, offk0, offk1);
                #pragma unroll
                for (int nf = 0; nf < 4; nf++)
                    b[nf] = read_bfrag(bp, ks, warp_n * 4 + nf, offk0, offk1);
                #pragma unroll
                for (int mf = 0; mf < 4; mf++)
                    #pragma unroll
                    for (int nf = 0; nf < 4; nf++)
                        mma_tf32(c[mf][nf], a[mf], b[nf]);
            }
            __syncthreads();
        }
    }

    // epilogue B: d2 = sq_i + sq_j - 2*dot; eud = d2>0 ? sqrt : 0 (diag forced 0)
    {
        float lemax = 0.0f;
        #pragma unroll
        for (int mf = 0; mf < 4; mf++) {
            int il = warp_m * 64 + mf * 16 + g;
            float q0 = s_sqi[il], q1 = s_sqi[il + 8];
            #pragma unroll
            for (int nf = 0; nf < 4; nf++) {
                int jl = warp_n * 32 + nf * 8 + 2 * tig;
                float r0 = s_sqj[jl], r1 = s_sqj[jl + 1];
                float d0 = q0 + r0 - 2.0f * c[mf][nf][0];
                float d1 = q0 + r1 - 2.0f * c[mf][nf][1];
                float d2_ = q1 + r0 - 2.0f * c[mf][nf][2];
                float d3 = q1 + r1 - 2.0f * c[mf][nf][3];
                float v0 = (d0 > 0.0f) ? sqrtf(d0) : 0.0f;
                float v1 = (d1 > 0.0f) ? sqrtf(d1) : 0.0f;
                float v2 = (d2_ > 0.0f) ? sqrtf(d2_) : 0.0f;
                float v3 = (d3 > 0.0f) ? sqrtf(d3) : 0.0f;
                if (i0 + il == j0 + jl) v0 = 0.0f;
                if (i0 + il == j0 + jl + 1) v1 = 0.0f;
                if (i0 + il + 8 == j0 + jl) v2 = 0.0f;
                if (i0 + il + 8 == j0 + jl + 1) v3 = 0.0f;
                lemax = fmaxf(lemax, fmaxf(fmaxf(v0, v1), fmaxf(v2, v3)));
                *(__half2*)&g_eud[(size_t)(i0 + il) * BSZ + j0 + jl]     = __floats2half2_rn(v0, v1);
                *(__half2*)&g_eud[(size_t)(i0 + il + 8) * BSZ + j0 + jl] = __floats2half2_rn(v2, v3);
                if (mirror) {
                    int f0 = (jl & 6) << 2, f1 = ((jl + 1) & 6) << 2;
                    smT[jl * 128 + (il ^ f0)]             = v0;
                    smT[(jl + 1) * 128 + (il ^ f1)]       = v1;
                    smT[jl * 128 + ((il + 8) ^ f0)]       = v2;
                    smT[(jl + 1) * 128 + ((il + 8) ^ f1)] = v3;
                }
            }
        }
        if (mirror) {
            __syncthreads();
            #pragma unroll
            for (int r = 0; r < 16; r++) {
                int row = wid * 16 + r;
                int cl = lane * 4;
                float4 v = *(const float4*)&smT[row * 128 + (cl ^ ((row & 6) << 2))];
                __half2 h01 = __floats2half2_rn(v.x, v.y);
                __half2 h23 = __floats2half2_rn(v.z, v.w);
                uint2 u = make_uint2(*(unsigned*)&h01, *(unsigned*)&h23);
                *(uint2*)&g_eud[(size_t)(j0 + row) * BSZ + i0 + cl] = u;
            }
        }
        #pragma unroll
        for (int off = 16; off; off >>= 1)
            lemax = fmaxf(lemax, __shfl_xor_sync(0xffffffffu, lemax, off));
        if (lane == 0) atomicMax(&g_emax_enc, fenc(lemax));
    }
}

// ---------------- kernel 3: per-row masked log-sum-exp losses (fp16 reads) ----------------
__device__ __forceinline__ void acc2(unsigned su, unsigned eu, float smin, float invr,
                                     float inve, float& p, float& n) {
    float2 s2 = __half22float2(*(__half2*)&su);
    float2 e2 = __half22float2(*(__half2*)&eu);
    float s, d;
    s = (s2.x - smin) * invr; d = e2.x * inve + s;
    if (s > 0.5f) p += __expf(d); else n += __expf(1.0f - d);
    s = (s2.y - smin) * invr; d = e2.y * inve + s;
    if (s > 0.5f) p += __expf(d); else n += __expf(1.0f - d);
}

__global__ __launch_bounds__(256) void loss_kernel() {
    const int row = blockIdx.x;
    const int t = threadIdx.x;
    const float smin = fdec(g_smin_enc);
    const float smax = fdec(g_smax_enc);
    const float emax = fdec(g_emax_enc);
    const float invr = 1.0f / (smax - smin);
    const float inve = 1.0f / emax;

    const uint4* srow = (const uint4*)(g_sim + (size_t)row * BSZ);  // 8 halves per uint4
    const uint4* erow = (const uint4*)(g_eud + (size_t)row * BSZ);

    float p = 0.0f, n = 0.0f;
    #pragma unroll
    for (int j = t; j < BSZ / 8; j += 256) {
        uint4 sv = srow[j];
        uint4 ev = erow[j];
        acc2(sv.x, ev.x, smin, invr, inve, p, n);
        acc2(sv.y, ev.y, smin, invr, inve, p, n);
        acc2(sv.z, ev.z, smin, invr, inve, p, n);
        acc2(sv.w, ev.w, smin, invr, inve, p, n);
    }
    #pragma unroll
    for (int off = 16; off; off >>= 1) {
        p += __shfl_xor_sync(0xffffffffu, p, off);
        n += __shfl_xor_sync(0xffffffffu, n, off);
    }
    __shared__ float sp[8], sn[8];
    if ((t & 31) == 0) { sp[t >> 5] = p; sn[t >> 5] = n; }
    __syncthreads();
    if (t == 0) {
        float P = 0.0f, N = 0.0f;
        #pragma unroll
        for (int w = 0; w < 8; w++) { P += sp[w]; N += sn[w]; }
        float lp = fmaxf(logf(P), 0.0f);
        float ln = fmaxf(logf(N), 0.0f);
        g_rowloss[row] = lp + ln;
    }
}

// ---------------- kernel 4: deterministic final mean ----------------
__global__ __launch_bounds__(256) void final_kernel(float* __restrict__ out) {
    __shared__ float s[256];
    const int t = threadIdx.x;
    float a = 0.0f;
    for (int i = t; i < BSZ; i += 256) a += g_rowloss[i];
    s[t] = a;
    __syncthreads();
    #pragma unroll
    for (int o = 128; o; o >>= 1) {
        if (t < o) s[t] += s[t + o];
        __syncthreads();
    }
    if (t == 0) out[0] = s[0] * (1.0f / (float)BSZ);
}

// ---------------- launch ----------------
extern "C" void kernel_launch(void* const* d_in, const int* in_sizes, int n_in,
                              void* d_out, int out_size) {
    const float* outputs = (const float*)d_in[0];
    const float* labels  = (const float*)d_in[1];
    if (n_in >= 2 && in_sizes[0] == BSZ * CDIM && in_sizes[1] == BSZ * DDIM) {
        const float* tmp = outputs; outputs = labels; labels = tmp;
    }
    float* out = (float*)d_out;

    cudaFuncSetAttribute(gram_mma, cudaFuncAttributeMaxDynamicSharedMemorySize, SM_BYTES);

    init_kernel<<<1, 1>>>();
    rownorm_kernel<<<BSZ, 256>>>(outputs, labels);
    gram_mma<<<dim3(64, 64), 256, SM_BYTES>>>(outputs, labels);
    loss_kernel<<<BSZ, 256>>>();
    final_kernel<<<1, 256>>>(out);
}

// round 5
// speedup vs baseline: 4.0302x; 1.5503x over previous
#include <cuda_runtime.h>
#include <cuda_fp16.h>
#include <cstdint>

#define BSZ 8192
#define CDIM 128
#define DDIM 256
#define TILE 128

// ---------------- scratch (static device globals; no allocation) ----------------
__device__ __half g_sim[(size_t)BSZ * BSZ];  // raw cosine-sim gram (128 MB, fp16)
__device__ __half g_eud[(size_t)BSZ * BSZ];  // raw euclidean distances (128 MB, fp16)
__device__ __half g_lab_h[(size_t)BSZ * CDIM];  // pre-normalized labels, fp16
__device__ __half g_out_h[(size_t)BSZ * DDIM];  // outputs, fp16
__device__ float g_sq[BSZ];                  // ||fp16(output_i)||^2 (fp32 accum)
__device__ float g_rowloss[BSZ];
__device__ unsigned g_smin_enc, g_smax_enc, g_emax_enc;

// monotone float <-> uint encoding so min/max reduce with integer atomics
__device__ __forceinline__ unsigned fenc(float f) {
    unsigned u = __float_as_uint(f);
    return (u & 0x80000000u) ? ~u : (u | 0x80000000u);
}
__device__ __forceinline__ float fdec(unsigned e) {
    unsigned u = (e & 0x80000000u) ? (e & 0x7FFFFFFFu) : ~e;
    return __uint_as_float(u);
}

__device__ __forceinline__ uint32_t smem_u32(const void* p) {
    uint32_t a;
    asm("{ .reg .u64 t; cvta.to.shared.u64 t, %1; cvt.u32.u64 %0, t; }" : "=r"(a) : "l"(p));
    return a;
}
__device__ __forceinline__ uint4 ldsm_x4(uint32_t addr) {
    uint4 r;
    asm volatile("ldmatrix.sync.aligned.m8n8.x4.shared.b16 {%0,%1,%2,%3}, [%4];"
                 : "=r"(r.x), "=r"(r.y), "=r"(r.z), "=r"(r.w) : "r"(addr));
    return r;
}
__device__ __forceinline__ void mma16(float* c, uint4 a, uint32_t b0, uint32_t b1) {
    asm volatile(
        "mma.sync.aligned.m16n8k16.row.col.f32.f16.f16.f32 "
        "{%0,%1,%2,%3}, {%4,%5,%6,%7}, {%8,%9}, {%0,%1,%2,%3};"
        : "+f"(c[0]), "+f"(c[1]), "+f"(c[2]), "+f"(c[3])
        : "r"(a.x), "r"(a.y), "r"(a.z), "r"(a.w), "r"(b0), "r"(b1));
}
#define CP_ASYNC16(dst, src) \
    asm volatile("cp.async.cg.shared.global [%0], [%1], 16;" :: "r"(dst), "l"(src))
#define CP_COMMIT() asm volatile("cp.async.commit_group;" ::: "memory")
#define CP_WAIT0()  asm volatile("cp.async.wait_group 0;" ::: "memory")

// ---------------- smem layout (bytes) ----------------
// stage: 2 bufs x (A 16KB + B 16KB) = 64KB ; smT (mirror, 16K floats) aliases stage
// s_sqi/s_sqj after stage
#define SM_STAGE_BYTES 65536
#define OFF_SQI 65536
#define OFF_SQJ 66048
#define SM_BYTES 66560

// copy one 128-row x 64-half tile into SW128-swizzled smem via cp.async
__device__ __forceinline__ void cpasync_tile(const __half* __restrict__ src, int ldh, int k0,
                                             uint32_t smem_dst, int tid) {
    #pragma unroll
    for (int it = 0; it < 4; it++) {
        int e = tid + 256 * it;                  // 0..1023 granules of 16B
        int row = e >> 3, gq = e & 7;
        const __half* g = src + (size_t)row * ldh + k0 + gq * 8;
        uint32_t bo = (uint32_t)(row * 128 + gq * 16);
        uint32_t dst = smem_dst + (bo ^ ((bo >> 3) & 0x70));
        CP_ASYNC16(dst, g);
    }
}

// ---------------- kernel 0: reset global reduction scalars ----------------
__global__ void init_kernel() {
    g_smin_enc = fenc(3.4e38f);
    g_smax_enc = fenc(-3.4e38f);
    g_emax_enc = fenc(0.0f);
}

// ---------------- kernel 1: per-row prep (norms + fp16 conversion) ----------------
__global__ __launch_bounds__(128) void rowprep_kernel(const float* __restrict__ outputs,
                                                      const float* __restrict__ labels) {
    const int row = blockIdx.x;
    const int t = threadIdx.x;
    __shared__ float red[4];
    __shared__ float s_invn;

    // labels: norm, then normalized fp16
    float l = labels[(size_t)row * CDIM + t];
    float lsum = l * l;
    #pragma unroll
    for (int off = 16; off; off >>= 1) lsum += __shfl_xor_sync(0xffffffffu, lsum, off);
    if ((t & 31) == 0) red[t >> 5] = lsum;
    __syncthreads();
    if (t == 0) {
        float L = red[0] + red[1] + red[2] + red[3];
        s_invn = 1.0f / (sqrtf(L) + 1e-12f);
    }
    __syncthreads();
    g_lab_h[(size_t)row * CDIM + t] = __float2half(l * s_invn);

    // outputs: fp16 copy + sq from rounded values
    float o0 = outputs[(size_t)row * DDIM + t];
    float o1 = outputs[(size_t)row * DDIM + 128 + t];
    __half h0 = __float2half(o0), h1 = __float2half(o1);
    g_out_h[(size_t)row * DDIM + t] = h0;
    g_out_h[(size_t)row * DDIM + 128 + t] = h1;
    float f0 = __half2float(h0), f1 = __half2float(h1);
    float osum = f0 * f0 + f1 * f1;
    #pragma unroll
    for (int off = 16; off; off >>= 1) osum += __shfl_xor_sync(0xffffffffu, osum, off);
    __syncthreads();
    if ((t & 31) == 0) red[t >> 5] = osum;
    __syncthreads();
    if (t == 0) g_sq[row] = red[0] + red[1] + red[2] + red[3];
}

// ---------------- kernel 2: fp16 mma fused upper-triangle grams ----------------
__global__ __launch_bounds__(256, 2) void gram_mma(const float* dummy0, const float* dummy1) {
    const int bi = blockIdx.y, bj = blockIdx.x;
    if (bj < bi) return;
    extern __shared__ float sm[];
    const uint32_t sb = smem_u32(sm);
    float* smT = sm;                               // aliases stage (after mainloop)
    float* s_sqi = (float*)((char*)sm + OFF_SQI);
    float* s_sqj = (float*)((char*)sm + OFF_SQJ);

    const int tid = threadIdx.x;
    const int wid = tid >> 5, lane = tid & 31;
    const int warp_m = wid >> 2, warp_n = wid & 3;
    const int g = lane >> 2, tig = lane & 3;
    const int i0 = bi * TILE, j0 = bj * TILE;
    const bool mirror = (bi != bj);

    if (tid < 128) {
        s_sqi[tid] = g_sq[i0 + tid];
        s_sqj[tid] = g_sq[j0 + tid];
    }

    // ldmatrix per-lane address precompute (byte offsets within 128x64h tile, 128B rows)
    const int laneA_row = lane & 15;
    const uint32_t baseA = (uint32_t)(((warp_m * 64 + laneA_row) << 7) + ((lane >> 4) << 4));
    const uint32_t xorA = (uint32_t)((laneA_row & 7) << 4);
    const int rowB = warp_n * 32 + ((lane >> 4) << 3) + (lane & 7);
    const uint32_t baseB = (uint32_t)((rowB << 7) + (((lane >> 3) & 1) << 4));
    const uint32_t xorB = (uint32_t)((rowB & 7) << 4);

    float c[4][4][4];

    // =============== Phase A: normalized-label gram (K=128, 2 chunks) ===============
    #pragma unroll
    for (int mf = 0; mf < 4; mf++)
        #pragma unroll
        for (int nf = 0; nf < 4; nf++)
            #pragma unroll
            for (int r = 0; r < 4; r++) c[mf][nf][r] = 0.0f;

    {
        const __half* Ai = g_lab_h + (size_t)i0 * CDIM;
        const __half* Bj = g_lab_h + (size_t)j0 * CDIM;
        cpasync_tile(Ai, CDIM, 0, sb, tid);
        cpasync_tile(Bj, CDIM, 0, sb + 16384, tid);
        CP_COMMIT();
        CP_WAIT0();
        __syncthreads();
        #pragma unroll
        for (int ch = 0; ch < 2; ch++) {
            if (ch + 1 < 2) {
                uint32_t nb = sb + ((ch + 1) & 1) * 32768;
                cpasync_tile(Ai, CDIM, (ch + 1) * 64, nb, tid);
                cpasync_tile(Bj, CDIM, (ch + 1) * 64, nb + 16384, tid);
                CP_COMMIT();
            }
            uint32_t sA = sb + (ch & 1) * 32768;
            uint32_t sB = sA + 16384;
            #pragma unroll
            for (int ks = 0; ks < 4; ks++) {
                uint4 a[4];
                #pragma unroll
                for (int mf = 0; mf < 4; mf++)
                    a[mf] = ldsm_x4(sA + ((baseA + mf * 2048 + ks * 32) ^ xorA));
                uint4 b0 = ldsm_x4(sB + ((baseB + ks * 32) ^ xorB));
                uint4 b1 = ldsm_x4(sB + ((baseB + 2048 + ks * 32) ^ xorB));
                #pragma unroll
                for (int mf = 0; mf < 4; mf++) {
                    mma16(c[mf][0], a[mf], b0.x, b0.y);
                    mma16(c[mf][1], a[mf], b0.z, b0.w);
                    mma16(c[mf][2], a[mf], b1.x, b1.y);
                    mma16(c[mf][3], a[mf], b1.z, b1.w);
                }
            }
            if (ch + 1 < 2) {
                CP_WAIT0();
                __syncthreads();
            }
        }
    }

    // epilogue A: c IS sim (labels pre-normalized); fp16 store + mirror; min/max
    {
        float lmin = 3.4e38f, lmax = -3.4e38f;
        __syncthreads();   // all warps done reading stage before smT alias writes
        #pragma unroll
        for (int mf = 0; mf < 4; mf++) {
            int il = warp_m * 64 + mf * 16 + g;
            #pragma unroll
            for (int nf = 0; nf < 4; nf++) {
                int jl = warp_n * 32 + nf * 8 + 2 * tig;
                float v0 = c[mf][nf][0], v1 = c[mf][nf][1];
                float v2 = c[mf][nf][2], v3 = c[mf][nf][3];
                lmin = fminf(lmin, fminf(fminf(v0, v1), fminf(v2, v3)));
                lmax = fmaxf(lmax, fmaxf(fmaxf(v0, v1), fmaxf(v2, v3)));
                *(__half2*)&g_sim[(size_t)(i0 + il) * BSZ + j0 + jl]     = __floats2half2_rn(v0, v1);
                *(__half2*)&g_sim[(size_t)(i0 + il + 8) * BSZ + j0 + jl] = __floats2half2_rn(v2, v3);
                if (mirror) {
                    int f0 = (jl & 6) << 2, f1 = ((jl + 1) & 6) << 2;
                    smT[jl * 128 + (il ^ f0)]             = v0;
                    smT[(jl + 1) * 128 + (il ^ f1)]       = v1;
                    smT[jl * 128 + ((il + 8) ^ f0)]       = v2;
                    smT[(jl + 1) * 128 + ((il + 8) ^ f1)] = v3;
                }
            }
        }
        if (mirror) {
            __syncthreads();
            #pragma unroll
            for (int r = 0; r < 16; r++) {
                int row = wid * 16 + r;
                int cl = lane * 4;
                float4 v = *(const float4*)&smT[row * 128 + (cl ^ ((row & 6) << 2))];
                __half2 h01 = __floats2half2_rn(v.x, v.y);
                __half2 h23 = __floats2half2_rn(v.z, v.w);
                uint2 u = make_uint2(*(unsigned*)&h01, *(unsigned*)&h23);
                *(uint2*)&g_sim[(size_t)(j0 + row) * BSZ + i0 + cl] = u;
            }
        }
        __syncthreads();
        #pragma unroll
        for (int off = 16; off; off >>= 1) {
            lmin = fminf(lmin, __shfl_xor_sync(0xffffffffu, lmin, off));
            lmax = fmaxf(lmax, __shfl_xor_sync(0xffffffffu, lmax, off));
        }
        if (lane == 0) {
            atomicMin(&g_smin_enc, fenc(lmin));
            atomicMax(&g_smax_enc, fenc(lmax));
        }
    }

    // =============== Phase B: output gram (K=256, 4 chunks) ===============
    #pragma unroll
    for (int mf = 0; mf < 4; mf++)
        #pragma unroll
        for (int nf = 0; nf < 4; nf++)
            #pragma unroll
            for (int r = 0; r < 4; r++) c[mf][nf][r] = 0.0f;

    {
        const __half* Ai = g_out_h + (size_t)i0 * DDIM;
        const __half* Bj = g_out_h + (size_t)j0 * DDIM;
        cpasync_tile(Ai, DDIM, 0, sb, tid);
        cpasync_tile(Bj, DDIM, 0, sb + 16384, tid);
        CP_COMMIT();
        CP_WAIT0();
        __syncthreads();
        #pragma unroll 1
        for (int ch = 0; ch < 4; ch++) {
            if (ch + 1 < 4) {
                uint32_t nb = sb + ((ch + 1) & 1) * 32768;
                cpasync_tile(Ai, DDIM, (ch + 1) * 64, nb, tid);
                cpasync_tile(Bj, DDIM, (ch + 1) * 64, nb + 16384, tid);
                CP_COMMIT();
            }
            uint32_t sA = sb + (ch & 1) * 32768;
            uint32_t sB = sA + 16384;
            #pragma unroll
            for (int ks = 0; ks < 4; ks++) {
                uint4 a[4];
                #pragma unroll
                for (int mf = 0; mf < 4; mf++)
                    a[mf] = ldsm_x4(sA + ((baseA + mf * 2048 + ks * 32) ^ xorA));
                uint4 b0 = ldsm_x4(sB + ((baseB + ks * 32) ^ xorB));
                uint4 b1 = ldsm_x4(sB + ((baseB + 2048 + ks * 32) ^ xorB));
                #pragma unroll
                for (int mf = 0; mf < 4; mf++) {
                    mma16(c[mf][0], a[mf], b0.x, b0.y);
                    mma16(c[mf][1], a[mf], b0.z, b0.w);
                    mma16(c[mf][2], a[mf], b1.x, b1.y);
                    mma16(c[mf][3], a[mf], b1.z, b1.w);
                }
            }
            if (ch + 1 < 4) {
                CP_WAIT0();
                __syncthreads();
            }
        }
    }

    // epilogue B: d2 = sq_i + sq_j - 2*dot; eud = d2>0 ? sqrt : 0 (diag forced 0)
    {
        float lemax = 0.0f;
        __syncthreads();   // stage reads done before smT alias writes
        #pragma unroll
        for (int mf = 0; mf < 4; mf++) {
            int il = warp_m * 64 + mf * 16 + g;
            float q0 = s_sqi[il], q1 = s_sqi[il + 8];
            #pragma unroll
            for (int nf = 0; nf < 4; nf++) {
                int jl = warp_n * 32 + nf * 8 + 2 * tig;
                float r0 = s_sqj[jl], r1 = s_sqj[jl + 1];
                float d0 = q0 + r0 - 2.0f * c[mf][nf][0];
                float d1 = q0 + r1 - 2.0f * c[mf][nf][1];
                float d2_ = q1 + r0 - 2.0f * c[mf][nf][2];
                float d3 = q1 + r1 - 2.0f * c[mf][nf][3];
                float v0 = (d0 > 0.0f) ? sqrtf(d0) : 0.0f;
                float v1 = (d1 > 0.0f) ? sqrtf(d1) : 0.0f;
                float v2 = (d2_ > 0.0f) ? sqrtf(d2_) : 0.0f;
                float v3 = (d3 > 0.0f) ? sqrtf(d3) : 0.0f;
                if (i0 + il == j0 + jl) v0 = 0.0f;
                if (i0 + il == j0 + jl + 1) v1 = 0.0f;
                if (i0 + il + 8 == j0 + jl) v2 = 0.0f;
                if (i0 + il + 8 == j0 + jl + 1) v3 = 0.0f;
                lemax = fmaxf(lemax, fmaxf(fmaxf(v0, v1), fmaxf(v2, v3)));
                *(__half2*)&g_eud[(size_t)(i0 + il) * BSZ + j0 + jl]     = __floats2half2_rn(v0, v1);
                *(__half2*)&g_eud[(size_t)(i0 + il + 8) * BSZ + j0 + jl] = __floats2half2_rn(v2, v3);
                if (mirror) {
                    int f0 = (jl & 6) << 2, f1 = ((jl + 1) & 6) << 2;
                    smT[jl * 128 + (il ^ f0)]             = v0;
                    smT[(jl + 1) * 128 + (il ^ f1)]       = v1;
                    smT[jl * 128 + ((il + 8) ^ f0)]       = v2;
                    smT[(jl + 1) * 128 + ((il + 8) ^ f1)] = v3;
                }
            }
        }
        if (mirror) {
            __syncthreads();
            #pragma unroll
            for (int r = 0; r < 16; r++) {
                int row = wid * 16 + r;
                int cl = lane * 4;
                float4 v = *(const float4*)&smT[row * 128 + (cl ^ ((row & 6) << 2))];
                __half2 h01 = __floats2half2_rn(v.x, v.y);
                __half2 h23 = __floats2half2_rn(v.z, v.w);
                uint2 u = make_uint2(*(unsigned*)&h01, *(unsigned*)&h23);
                *(uint2*)&g_eud[(size_t)(j0 + row) * BSZ + i0 + cl] = u;
            }
        }
        #pragma unroll
        for (int off = 16; off; off >>= 1)
            lemax = fmaxf(lemax, __shfl_xor_sync(0xffffffffu, lemax, off));
        if (lane == 0) atomicMax(&g_emax_enc, fenc(lemax));
    }
}

// ---------------- kernel 3: per-row masked log-sum-exp losses (fp16 reads) ----------------
__device__ __forceinline__ void acc2(unsigned su, unsigned eu, float smin, float invr,
                                     float inve, float& p, float& n) {
    float2 s2 = __half22float2(*(__half2*)&su);
    float2 e2 = __half22float2(*(__half2*)&eu);
    float s, d;
    s = (s2.x - smin) * invr; d = e2.x * inve + s;
    if (s > 0.5f) p += __expf(d); else n += __expf(1.0f - d);
    s = (s2.y - smin) * invr; d = e2.y * inve + s;
    if (s > 0.5f) p += __expf(d); else n += __expf(1.0f - d);
}

__global__ __launch_bounds__(256) void loss_kernel() {
    const int row = blockIdx.x;
    const int t = threadIdx.x;
    const float smin = fdec(g_smin_enc);
    const float smax = fdec(g_smax_enc);
    const float emax = fdec(g_emax_enc);
    const float invr = 1.0f / (smax - smin);
    const float inve = 1.0f / emax;

    const uint4* srow = (const uint4*)(g_sim + (size_t)row * BSZ);
    const uint4* erow = (const uint4*)(g_eud + (size_t)row * BSZ);

    float p = 0.0f, n = 0.0f;
    #pragma unroll
    for (int j = t; j < BSZ / 8; j += 256) {
        uint4 sv = srow[j];
        uint4 ev = erow[j];
        acc2(sv.x, ev.x, smin, invr, inve, p, n);
        acc2(sv.y, ev.y, smin, invr, inve, p, n);
        acc2(sv.z, ev.z, smin, invr, inve, p, n);
        acc2(sv.w, ev.w, smin, invr, inve, p, n);
    }
    #pragma unroll
    for (int off = 16; off; off >>= 1) {
        p += __shfl_xor_sync(0xffffffffu, p, off);
        n += __shfl_xor_sync(0xffffffffu, n, off);
    }
    __shared__ float sp[8], sn[8];
    if ((t & 31) == 0) { sp[t >> 5] = p; sn[t >> 5] = n; }
    __syncthreads();
    if (t == 0) {
        float P = 0.0f, N = 0.0f;
        #pragma unroll
        for (int w = 0; w < 8; w++) { P += sp[w]; N += sn[w]; }
        float lp = fmaxf(logf(P), 0.0f);
        float ln = fmaxf(logf(N), 0.0f);
        g_rowloss[row] = lp + ln;
    }
}

// ---------------- kernel 4: deterministic final mean ----------------
__global__ __launch_bounds__(256) void final_kernel(float* __restrict__ out) {
    __shared__ float s[256];
    const int t = threadIdx.x;
    float a = 0.0f;
    for (int i = t; i < BSZ; i += 256) a += g_rowloss[i];
    s[t] = a;
    __syncthreads();
    #pragma unroll
    for (int o = 128; o; o >>= 1) {
        if (t < o) s[t] += s[t + o];
        __syncthreads();
    }
    if (t == 0) out[0] = s[0] * (1.0f / (float)BSZ);
}

// ---------------- launch ----------------
extern "C" void kernel_launch(void* const* d_in, const int* in_sizes, int n_in,
                              void* d_out, int out_size) {
    const float* outputs = (const float*)d_in[0];
    const float* labels  = (const float*)d_in[1];
    if (n_in >= 2 && in_sizes[0] == BSZ * CDIM && in_sizes[1] == BSZ * DDIM) {
        const float* tmp = outputs; outputs = labels; labels = tmp;
    }
    float* out = (float*)d_out;

    cudaFuncSetAttribute(gram_mma, cudaFuncAttributeMaxDynamicSharedMemorySize, SM_BYTES);

    init_kernel<<<1, 1>>>();
    rowprep_kernel<<<BSZ, 128>>>(outputs, labels);
    gram_mma<<<dim3(64, 64), 256, SM_BYTES>>>(outputs, labels);
    loss_kernel<<<BSZ, 256>>>();
    final_kernel<<<1, 256>>>(out);
}

// round 6
// speedup vs baseline: 4.4886x; 1.1137x over previous
#include <cuda_runtime.h>
#include <cuda_fp16.h>
#include <cstdint>

#define BSZ 8192
#define CDIM 128
#define DDIM 256
#define TILE 128

// ---------------- scratch (static device globals; no allocation) ----------------
__device__ unsigned g_se[(size_t)BSZ * BSZ];    // packed (sim fp16 | eud fp16) (256 MB)
__device__ __half g_lab_h[(size_t)BSZ * CDIM];  // pre-normalized labels, fp16
__device__ __half g_out_h[(size_t)BSZ * DDIM];  // outputs, fp16
__device__ float g_sq[BSZ];                     // ||fp16(output_i)||^2 (fp32 accum)
__device__ float g_rowloss[BSZ];
__device__ unsigned g_smin_enc, g_smax_enc, g_emax_enc;

// monotone float <-> uint encoding so min/max reduce with integer atomics
__device__ __forceinline__ unsigned fenc(float f) {
    unsigned u = __float_as_uint(f);
    return (u & 0x80000000u) ? ~u : (u | 0x80000000u);
}
__device__ __forceinline__ float fdec(unsigned e) {
    unsigned u = (e & 0x80000000u) ? (e & 0x7FFFFFFFu) : ~e;
    return __uint_as_float(u);
}

__device__ __forceinline__ uint32_t smem_u32(const void* p) {
    uint32_t a;
    asm("{ .reg .u64 t; cvta.to.shared.u64 t, %1; cvt.u32.u64 %0, t; }" : "=r"(a) : "l"(p));
    return a;
}
__device__ __forceinline__ uint4 ldsm_x4(uint32_t addr) {
    uint4 r;
    asm volatile("ldmatrix.sync.aligned.m8n8.x4.shared.b16 {%0,%1,%2,%3}, [%4];"
                 : "=r"(r.x), "=r"(r.y), "=r"(r.z), "=r"(r.w) : "r"(addr));
    return r;
}
__device__ __forceinline__ void mma16(float* c, uint4 a, uint32_t b0, uint32_t b1) {
    asm volatile(
        "mma.sync.aligned.m16n8k16.row.col.f32.f16.f16.f32 "
        "{%0,%1,%2,%3}, {%4,%5,%6,%7}, {%8,%9}, {%0,%1,%2,%3};"
        : "+f"(c[0]), "+f"(c[1]), "+f"(c[2]), "+f"(c[3])
        : "r"(a.x), "r"(a.y), "r"(a.z), "r"(a.w), "r"(b0), "r"(b1));
}
#define CP_ASYNC16(dst, src) \
    asm volatile("cp.async.cg.shared.global [%0], [%1], 16;" :: "r"(dst), "l"(src))
#define CP_COMMIT() asm volatile("cp.async.commit_group;" ::: "memory")
#define CP_WAIT0()  asm volatile("cp.async.wait_group 0;" ::: "memory")

// ---------------- smem layout (bytes) ----------------
// stage: 2 bufs x (A 16KB + B 16KB) = 64KB at [0, 65536)
// smT (mirror transpose, 128x128 uints = 64KB) aliases stage after mainloop B
// stash: sim tile, thread-private, 32 uints x 256 threads = 32KB
#define OFF_STASH 65536
#define OFF_SQI   98304
#define OFF_SQJ   98816
#define SM_BYTES  99328

// copy one 128-row x 64-half tile into SW128-swizzled smem via cp.async
__device__ __forceinline__ void cpasync_tile(const __half* __restrict__ src, int ldh, int k0,
                                             uint32_t smem_dst, int tid) {
    #pragma unroll
    for (int it = 0; it < 4; it++) {
        int e = tid + 256 * it;                  // 0..1023 granules of 16B
        int row = e >> 3, gq = e & 7;
        const __half* g = src + (size_t)row * ldh + k0 + gq * 8;
        uint32_t bo = (uint32_t)(row * 128 + gq * 16);
        uint32_t dst = smem_dst + (bo ^ ((bo >> 3) & 0x70));
        CP_ASYNC16(dst, g);
    }
}

__device__ __forceinline__ unsigned pack_se(unsigned simlo16, float e) {
    unsigned eh = (unsigned)__half_as_ushort(__float2half_rn(e));
    return (simlo16 & 0xFFFFu) | (eh << 16);
}

// ---------------- kernel 0: reset global reduction scalars ----------------
__global__ void init_kernel() {
    g_smin_enc = fenc(3.4e38f);
    g_smax_enc = fenc(-3.4e38f);
    g_emax_enc = fenc(0.0f);
}

// ---------------- kernel 1: per-row prep (norms + fp16 conversion) ----------------
__global__ __launch_bounds__(128) void rowprep_kernel(const float* __restrict__ outputs,
                                                      const float* __restrict__ labels) {
    const int row = blockIdx.x;
    const int t = threadIdx.x;
    __shared__ float red[4];
    __shared__ float s_invn;

    float l = labels[(size_t)row * CDIM + t];
    float lsum = l * l;
    #pragma unroll
    for (int off = 16; off; off >>= 1) lsum += __shfl_xor_sync(0xffffffffu, lsum, off);
    if ((t & 31) == 0) red[t >> 5] = lsum;
    __syncthreads();
    if (t == 0) {
        float L = red[0] + red[1] + red[2] + red[3];
        s_invn = 1.0f / (sqrtf(L) + 1e-12f);
    }
    __syncthreads();
    g_lab_h[(size_t)row * CDIM + t] = __float2half(l * s_invn);

    float o0 = outputs[(size_t)row * DDIM + t];
    float o1 = outputs[(size_t)row * DDIM + 128 + t];
    __half h0 = __float2half(o0), h1 = __float2half(o1);
    g_out_h[(size_t)row * DDIM + t] = h0;
    g_out_h[(size_t)row * DDIM + 128 + t] = h1;
    float f0 = __half2float(h0), f1 = __half2float(h1);
    float osum = f0 * f0 + f1 * f1;
    #pragma unroll
    for (int off = 16; off; off >>= 1) osum += __shfl_xor_sync(0xffffffffu, osum, off);
    __syncthreads();
    if ((t & 31) == 0) red[t >> 5] = osum;
    __syncthreads();
    if (t == 0) g_sq[row] = red[0] + red[1] + red[2] + red[3];
}

// ---------------- kernel 2: fp16 mma fused upper-triangle grams, packed output ----------------
__global__ __launch_bounds__(256, 2) void gram_mma(const float* dummy0, const float* dummy1) {
    const int bi = blockIdx.y, bj = blockIdx.x;
    if (bj < bi) return;
    extern __shared__ float sm[];
    const uint32_t sb = smem_u32(sm);
    uint32_t* smTu   = (uint32_t*)sm;                       // aliases stage after mainloop B
    uint32_t* stash  = (uint32_t*)((char*)sm + OFF_STASH);  // thread-private sim tile
    float* s_sqi = (float*)((char*)sm + OFF_SQI);
    float* s_sqj = (float*)((char*)sm + OFF_SQJ);

    const int tid = threadIdx.x;
    const int wid = tid >> 5, lane = tid & 31;
    const int warp_m = wid >> 2, warp_n = wid & 3;
    const int g = lane >> 2, tig = lane & 3;
    const int i0 = bi * TILE, j0 = bj * TILE;
    const bool mirror = (bi != bj);

    if (tid < 128) {
        s_sqi[tid] = g_sq[i0 + tid];
        s_sqj[tid] = g_sq[j0 + tid];
    }

    // ldmatrix per-lane address precompute (byte offsets within 128x64h tile, 128B rows)
    const int laneA_row = lane & 15;
    const uint32_t baseA = (uint32_t)(((warp_m * 64 + laneA_row) << 7) + ((lane >> 4) << 4));
    const uint32_t xorA = (uint32_t)((laneA_row & 7) << 4);
    const int rowB = warp_n * 32 + ((lane >> 4) << 3) + (lane & 7);
    const uint32_t baseB = (uint32_t)((rowB << 7) + (((lane >> 3) & 1) << 4));
    const uint32_t xorB = (uint32_t)((rowB & 7) << 4);

    float c[4][4][4];

    // =============== Phase A: normalized-label gram (K=128, 2 chunks) ===============
    #pragma unroll
    for (int mf = 0; mf < 4; mf++)
        #pragma unroll
        for (int nf = 0; nf < 4; nf++)
            #pragma unroll
            for (int r = 0; r < 4; r++) c[mf][nf][r] = 0.0f;

    {
        const __half* Ai = g_lab_h + (size_t)i0 * CDIM;
        const __half* Bj = g_lab_h + (size_t)j0 * CDIM;
        cpasync_tile(Ai, CDIM, 0, sb, tid);
        cpasync_tile(Bj, CDIM, 0, sb + 16384, tid);
        CP_COMMIT();
        CP_WAIT0();
        __syncthreads();
        #pragma unroll
        for (int ch = 0; ch < 2; ch++) {
            if (ch + 1 < 2) {
                uint32_t nb = sb + ((ch + 1) & 1) * 32768;
                cpasync_tile(Ai, CDIM, (ch + 1) * 64, nb, tid);
                cpasync_tile(Bj, CDIM, (ch + 1) * 64, nb + 16384, tid);
                CP_COMMIT();
            }
            uint32_t sA = sb + (ch & 1) * 32768;
            uint32_t sB = sA + 16384;
            #pragma unroll
            for (int ks = 0; ks < 4; ks++) {
                uint4 a[4];
                #pragma unroll
                for (int mf = 0; mf < 4; mf++)
                    a[mf] = ldsm_x4(sA + ((baseA + mf * 2048 + ks * 32) ^ xorA));
                uint4 b0 = ldsm_x4(sB + ((baseB + ks * 32) ^ xorB));
                uint4 b1 = ldsm_x4(sB + ((baseB + 2048 + ks * 32) ^ xorB));
                #pragma unroll
                for (int mf = 0; mf < 4; mf++) {
                    mma16(c[mf][0], a[mf], b0.x, b0.y);
                    mma16(c[mf][1], a[mf], b0.z, b0.w);
                    mma16(c[mf][2], a[mf], b1.x, b1.y);
                    mma16(c[mf][3], a[mf], b1.z, b1.w);
                }
            }
            if (ch + 1 < 2) {
                CP_WAIT0();
                __syncthreads();
            }
        }
    }

    // epilogue A: min/max reduce + stash sim tile (thread-private, conflict-free)
    {
        float lmin = 3.4e38f, lmax = -3.4e38f;
        #pragma unroll
        for (int mf = 0; mf < 4; mf++) {
            #pragma unroll
            for (int nf = 0; nf < 4; nf++) {
                float v0 = c[mf][nf][0], v1 = c[mf][nf][1];
                float v2 = c[mf][nf][2], v3 = c[mf][nf][3];
                lmin = fminf(lmin, fminf(fminf(v0, v1), fminf(v2, v3)));
                lmax = fmaxf(lmax, fmaxf(fmaxf(v0, v1), fmaxf(v2, v3)));
                int idx0 = (mf * 4 + nf) * 2;
                __half2 h01 = __floats2half2_rn(v0, v1);
                __half2 h23 = __floats2half2_rn(v2, v3);
                stash[idx0 * 256 + tid]       = *(unsigned*)&h01;
                stash[(idx0 + 1) * 256 + tid] = *(unsigned*)&h23;
            }
        }
        #pragma unroll
        for (int off = 16; off; off >>= 1) {
            lmin = fminf(lmin, __shfl_xor_sync(0xffffffffu, lmin, off));
            lmax = fmaxf(lmax, __shfl_xor_sync(0xffffffffu, lmax, off));
        }
        if (lane == 0) {
            atomicMin(&g_smin_enc, fenc(lmin));
            atomicMax(&g_smax_enc, fenc(lmax));
        }
    }

    // =============== Phase B: output gram (K=256, 4 chunks) ===============
    #pragma unroll
    for (int mf = 0; mf < 4; mf++)
        #pragma unroll
        for (int nf = 0; nf < 4; nf++)
            #pragma unroll
            for (int r = 0; r < 4; r++) c[mf][nf][r] = 0.0f;

    {
        const __half* Ai = g_out_h + (size_t)i0 * DDIM;
        const __half* Bj = g_out_h + (size_t)j0 * DDIM;
        cpasync_tile(Ai, DDIM, 0, sb, tid);
        cpasync_tile(Bj, DDIM, 0, sb + 16384, tid);
        CP_COMMIT();
        CP_WAIT0();
        __syncthreads();
        #pragma unroll 1
        for (int ch = 0; ch < 4; ch++) {
            if (ch + 1 < 4) {
                uint32_t nb = sb + ((ch + 1) & 1) * 32768;
                cpasync_tile(Ai, DDIM, (ch + 1) * 64, nb, tid);
                cpasync_tile(Bj, DDIM, (ch + 1) * 64, nb + 16384, tid);
                CP_COMMIT();
            }
            uint32_t sA = sb + (ch & 1) * 32768;
            uint32_t sB = sA + 16384;
            #pragma unroll
            for (int ks = 0; ks < 4; ks++) {
                uint4 a[4];
                #pragma unroll
                for (int mf = 0; mf < 4; mf++)
                    a[mf] = ldsm_x4(sA + ((baseA + mf * 2048 + ks * 32) ^ xorA));
                uint4 b0 = ldsm_x4(sB + ((baseB + ks * 32) ^ xorB));
                uint4 b1 = ldsm_x4(sB + ((baseB + 2048 + ks * 32) ^ xorB));
                #pragma unroll
                for (int mf = 0; mf < 4; mf++) {
                    mma16(c[mf][0], a[mf], b0.x, b0.y);
                    mma16(c[mf][1], a[mf], b0.z, b0.w);
                    mma16(c[mf][2], a[mf], b1.x, b1.y);
                    mma16(c[mf][3], a[mf], b1.z, b1.w);
                }
            }
            if (ch + 1 < 4) {
                CP_WAIT0();
                __syncthreads();
            }
        }
    }

    // epilogue B (single store pass): eud + packed (sim|eud) upper store + one mirror transpose
    {
        float lemax = 0.0f;
        __syncthreads();   // all warps done reading stage before smTu alias writes
        #pragma unroll
        for (int mf = 0; mf < 4; mf++) {
            int il = warp_m * 64 + mf * 16 + g;
            float q0 = s_sqi[il], q1 = s_sqi[il + 8];
            #pragma unroll
            for (int nf = 0; nf < 4; nf++) {
                int jl = warp_n * 32 + nf * 8 + 2 * tig;
                float r0 = s_sqj[jl], r1 = s_sqj[jl + 1];
                float d0 = q0 + r0 - 2.0f * c[mf][nf][0];
                float d1 = q0 + r1 - 2.0f * c[mf][nf][1];
                float d2_ = q1 + r0 - 2.0f * c[mf][nf][2];
                float d3 = q1 + r1 - 2.0f * c[mf][nf][3];
                float v0 = (d0 > 0.0f) ? sqrtf(d0) : 0.0f;
                float v1 = (d1 > 0.0f) ? sqrtf(d1) : 0.0f;
                float v2 = (d2_ > 0.0f) ? sqrtf(d2_) : 0.0f;
                float v3 = (d3 > 0.0f) ? sqrtf(d3) : 0.0f;
                if (i0 + il == j0 + jl) v0 = 0.0f;
                if (i0 + il == j0 + jl + 1) v1 = 0.0f;
                if (i0 + il + 8 == j0 + jl) v2 = 0.0f;
                if (i0 + il + 8 == j0 + jl + 1) v3 = 0.0f;
                lemax = fmaxf(lemax, fmaxf(fmaxf(v0, v1), fmaxf(v2, v3)));

                int idx0 = (mf * 4 + nf) * 2;
                unsigned sp01 = stash[idx0 * 256 + tid];
                unsigned sp23 = stash[(idx0 + 1) * 256 + tid];
                unsigned u0 = pack_se(sp01, v0);
                unsigned u1 = pack_se(sp01 >> 16, v1);
                unsigned u2 = pack_se(sp23, v2);
                unsigned u3 = pack_se(sp23 >> 16, v3);

                *(uint2*)&g_se[(size_t)(i0 + il) * BSZ + j0 + jl]     = make_uint2(u0, u1);
                *(uint2*)&g_se[(size_t)(i0 + il + 8) * BSZ + j0 + jl] = make_uint2(u2, u3);
                if (mirror) {
                    int f0 = (jl & 6) << 2, f1 = ((jl + 1) & 6) << 2;
                    smTu[jl * 128 + (il ^ f0)]             = u0;
                    smTu[(jl + 1) * 128 + (il ^ f1)]       = u1;
                    smTu[jl * 128 + ((il + 8) ^ f0)]       = u2;
                    smTu[(jl + 1) * 128 + ((il + 8) ^ f1)] = u3;
                }
            }
        }
        if (mirror) {
            __syncthreads();
            #pragma unroll
            for (int r = 0; r < 16; r++) {
                int row = wid * 16 + r;
                int cl = lane * 4;
                uint4 v = *(const uint4*)&smTu[row * 128 + (cl ^ ((row & 6) << 2))];
                *(uint4*)&g_se[(size_t)(j0 + row) * BSZ + i0 + cl] = v;
            }
        }
        #pragma unroll
        for (int off = 16; off; off >>= 1)
            lemax = fmaxf(lemax, __shfl_xor_sync(0xffffffffu, lemax, off));
        if (lane == 0) atomicMax(&g_emax_enc, fenc(lemax));
    }
}

// ---------------- kernel 3: per-row masked log-sum-exp losses (packed stream) ----------------
__device__ __forceinline__ void acc_se(unsigned u, float c0, float c1, float c2,
                                       float sthr, float& p, float& n) {
    const float L2E = 1.4426950408889634f;
    float2 f = __half22float2(*(__half2*)&u);   // f.x = sim, f.y = eud
    float t = fmaf(f.x, c1, c0);
    float d = fmaf(f.y, c2, t);
    bool pos = f.x > sthr;
    float arg = pos ? d : (L2E - d);
    float v = exp2f(arg);
    p += pos ? v : 0.0f;
    n += pos ? 0.0f : v;
}

__global__ __launch_bounds__(256) void loss_kernel() {
    const int row = blockIdx.x;
    const int t = threadIdx.x;
    const float L2E = 1.4426950408889634f;
    const float smin = fdec(g_smin_enc);
    const float smax = fdec(g_smax_enc);
    const float emax = fdec(g_emax_enc);
    const float c1 = L2E / (smax - smin);
    const float c0 = -smin * c1;
    const float c2 = L2E / emax;
    const float sthr = smin + 0.5f * (smax - smin);

    const uint4* srow = (const uint4*)(g_se + (size_t)row * BSZ);

    float p = 0.0f, n = 0.0f;
    #pragma unroll
    for (int j = t; j < BSZ / 4; j += 256) {
        uint4 v = srow[j];
        acc_se(v.x, c0, c1, c2, sthr, p, n);
        acc_se(v.y, c0, c1, c2, sthr, p, n);
        acc_se(v.z, c0, c1, c2, sthr, p, n);
        acc_se(v.w, c0, c1, c2, sthr, p, n);
    }
    #pragma unroll
    for (int off = 16; off; off >>= 1) {
        p += __shfl_xor_sync(0xffffffffu, p, off);
        n += __shfl_xor_sync(0xffffffffu, n, off);
    }
    __shared__ float sp[8], sn[8];
    if ((t & 31) == 0) { sp[t >> 5] = p; sn[t >> 5] = n; }
    __syncthreads();
    if (t == 0) {
        float P = 0.0f, N = 0.0f;
        #pragma unroll
        for (int w = 0; w < 8; w++) { P += sp[w]; N += sn[w]; }
        float lp = fmaxf(logf(P), 0.0f);
        float ln = fmaxf(logf(N), 0.0f);
        g_rowloss[row] = lp + ln;
    }
}

// ---------------- kernel 4: deterministic final mean ----------------
__global__ __launch_bounds__(256) void final_kernel(float* __restrict__ out) {
    __shared__ float s[256];
    const int t = threadIdx.x;
    float a = 0.0f;
    for (int i = t; i < BSZ; i += 256) a += g_rowloss[i];
    s[t] = a;
    __syncthreads();
    #pragma unroll
    for (int o = 128; o; o >>= 1) {
        if (t < o) s[t] += s[t + o];
        __syncthreads();
    }
    if (t == 0) out[0] = s[0] * (1.0f / (float)BSZ);
}

// ---------------- launch ----------------
extern "C" void kernel_launch(void* const* d_in, const int* in_sizes, int n_in,
                              void* d_out, int out_size) {
    const float* outputs = (const float*)d_in[0];
    const float* labels  = (const float*)d_in[1];
    if (n_in >= 2 && in_sizes[0] == BSZ * CDIM && in_sizes[1] == BSZ * DDIM) {
        const float* tmp = outputs; outputs = labels; labels = tmp;
    }
    float* out = (float*)d_out;

    cudaFuncSetAttribute(gram_mma, cudaFuncAttributeMaxDynamicSharedMemorySize, SM_BYTES);

    init_kernel<<<1, 1>>>();
    rowprep_kernel<<<BSZ, 128>>>(outputs, labels);
    gram_mma<<<dim3(64, 64), 256, SM_BYTES>>>(outputs, labels);
    loss_kernel<<<BSZ, 256>>>();
    final_kernel<<<1, 256>>>(out);
}

// round 7
// speedup vs baseline: 5.4049x; 1.2042x over previous
#include <cuda_runtime.h>
#include <cuda_fp16.h>
#include <cstdint>

#define BSZ 8192
#define CDIM 128
#define DDIM 256
#define TILE 128
#define NTILE 64          // BSZ / TILE
#define NPAIRS 2080       // NTILE*(NTILE+1)/2

// ---------------- scratch (static device globals; no allocation) ----------------
__device__ unsigned g_se[(size_t)BSZ * BSZ];    // packed (sim fp16 | eud fp16); upper tiles only
__device__ __half g_lab_h[(size_t)BSZ * CDIM];  // pre-normalized labels, fp16
__device__ __half g_out_h[(size_t)BSZ * DDIM];  // outputs, fp16
__device__ float g_sq[BSZ];                     // ||fp16(output_i)||^2 (fp32 accum)
__device__ float2 g_part[(size_t)BSZ * NTILE];  // per-(row, tile) partial (pos, neg) sums
__device__ float g_rowloss[BSZ];
__device__ unsigned g_smin_enc, g_smax_enc, g_emax_enc;

// monotone float <-> uint encoding so min/max reduce with integer atomics
__device__ __forceinline__ unsigned fenc(float f) {
    unsigned u = __float_as_uint(f);
    return (u & 0x80000000u) ? ~u : (u | 0x80000000u);
}
__device__ __forceinline__ float fdec(unsigned e) {
    unsigned u = (e & 0x80000000u) ? (e & 0x7FFFFFFFu) : ~e;
    return __uint_as_float(u);
}

// triangular pair decode: k in [0, NPAIRS) -> (a, b) with 0 <= a <= b < NTILE
__device__ __forceinline__ int tri_off(int a) { return a * NTILE - (a * (a - 1)) / 2; }
__device__ __forceinline__ void tri_decode(int k, int& a, int& b) {
    int aa = (int)((129.0f - sqrtf(16641.0f - 8.0f * (float)k)) * 0.5f);
    aa = max(0, min(63, aa));
    while (aa < 63 && tri_off(aa + 1) <= k) aa++;
    while (aa > 0 && tri_off(aa) > k) aa--;
    a = aa;
    b = aa + (k - tri_off(aa));
}

__device__ __forceinline__ uint32_t smem_u32(const void* p) {
    uint32_t a;
    asm("{ .reg .u64 t; cvta.to.shared.u64 t, %1; cvt.u32.u64 %0, t; }" : "=r"(a) : "l"(p));
    return a;
}
__device__ __forceinline__ uint4 ldsm_x4(uint32_t addr) {
    uint4 r;
    asm volatile("ldmatrix.sync.aligned.m8n8.x4.shared.b16 {%0,%1,%2,%3}, [%4];"
                 : "=r"(r.x), "=r"(r.y), "=r"(r.z), "=r"(r.w) : "r"(addr));
    return r;
}
__device__ __forceinline__ void mma16(float* c, uint4 a, uint32_t b0, uint32_t b1) {
    asm volatile(
        "mma.sync.aligned.m16n8k16.row.col.f32.f16.f16.f32 "
        "{%0,%1,%2,%3}, {%4,%5,%6,%7}, {%8,%9}, {%0,%1,%2,%3};"
        : "+f"(c[0]), "+f"(c[1]), "+f"(c[2]), "+f"(c[3])
        : "r"(a.x), "r"(a.y), "r"(a.z), "r"(a.w), "r"(b0), "r"(b1));
}
#define CP_ASYNC16(dst, src) \
    asm volatile("cp.async.cg.shared.global [%0], [%1], 16;" :: "r"(dst), "l"(src))
#define CP_COMMIT() asm volatile("cp.async.commit_group;" ::: "memory")
#define CP_WAIT0()  asm volatile("cp.async.wait_group 0;" ::: "memory")

// ---------------- gram smem layout (bytes) ----------------
#define OFF_STASH 65536
#define OFF_SQI   98304
#define OFF_SQJ   98816
#define SM_BYTES  99328

// copy one 128-row x 64-half tile into SW128-swizzled smem via cp.async
__device__ __forceinline__ void cpasync_tile(const __half* __restrict__ src, int ldh, int k0,
                                             uint32_t smem_dst, int tid) {
    #pragma unroll
    for (int it = 0; it < 4; it++) {
        int e = tid + 256 * it;                  // 0..1023 granules of 16B
        int row = e >> 3, gq = e & 7;
        const __half* g = src + (size_t)row * ldh + k0 + gq * 8;
        uint32_t bo = (uint32_t)(row * 128 + gq * 16);
        uint32_t dst = smem_dst + (bo ^ ((bo >> 3) & 0x70));
        CP_ASYNC16(dst, g);
    }
}

__device__ __forceinline__ unsigned pack_se(unsigned simlo16, float e) {
    unsigned eh = (unsigned)__half_as_ushort(__float2half_rn(e));
    return (simlo16 & 0xFFFFu) | (eh << 16);
}

// ---------------- kernel 0: reset global reduction scalars ----------------
__global__ void init_kernel() {
    g_smin_enc = fenc(3.4e38f);
    g_smax_enc = fenc(-3.4e38f);
    g_emax_enc = fenc(0.0f);
}

// ---------------- kernel 1: per-row prep (norms + fp16 conversion) ----------------
__global__ __launch_bounds__(128) void rowprep_kernel(const float* __restrict__ outputs,
                                                      const float* __restrict__ labels) {
    const int row = blockIdx.x;
    const int t = threadIdx.x;
    __shared__ float red[4];
    __shared__ float s_invn;

    float l = labels[(size_t)row * CDIM + t];
    float lsum = l * l;
    #pragma unroll
    for (int off = 16; off; off >>= 1) lsum += __shfl_xor_sync(0xffffffffu, lsum, off);
    if ((t & 31) == 0) red[t >> 5] = lsum;
    __syncthreads();
    if (t == 0) {
        float L = red[0] + red[1] + red[2] + red[3];
        s_invn = 1.0f / (sqrtf(L) + 1e-12f);
    }
    __syncthreads();
    g_lab_h[(size_t)row * CDIM + t] = __float2half(l * s_invn);

    float o0 = outputs[(size_t)row * DDIM + t];
    float o1 = outputs[(size_t)row * DDIM + 128 + t];
    __half h0 = __float2half(o0), h1 = __float2half(o1);
    g_out_h[(size_t)row * DDIM + t] = h0;
    g_out_h[(size_t)row * DDIM + 128 + t] = h1;
    float f0 = __half2float(h0), f1 = __half2float(h1);
    float osum = f0 * f0 + f1 * f1;
    #pragma unroll
    for (int off = 16; off; off >>= 1) osum += __shfl_xor_sync(0xffffffffu, osum, off);
    __syncthreads();
    if ((t & 31) == 0) red[t >> 5] = osum;
    __syncthreads();
    if (t == 0) g_sq[row] = red[0] + red[1] + red[2] + red[3];
}

// ---------------- kernel 2: fp16 mma fused grams, upper tiles only ----------------
__global__ __launch_bounds__(256, 2) void gram_mma() {
    int bi, bj;
    tri_decode(blockIdx.x, bi, bj);
    extern __shared__ float sm[];
    const uint32_t sb = smem_u32(sm);
    uint32_t* stash  = (uint32_t*)((char*)sm + OFF_STASH);  // thread-private sim tile
    float* s_sqi = (float*)((char*)sm + OFF_SQI);
    float* s_sqj = (float*)((char*)sm + OFF_SQJ);

    const int tid = threadIdx.x;
    const int wid = tid >> 5, lane = tid & 31;
    const int warp_m = wid >> 2, warp_n = wid & 3;
    const int g = lane >> 2, tig = lane & 3;
    const int i0 = bi * TILE, j0 = bj * TILE;

    if (tid < 128) {
        s_sqi[tid] = g_sq[i0 + tid];
        s_sqj[tid] = g_sq[j0 + tid];
    }

    // ldmatrix per-lane address precompute (byte offsets within 128x64h tile, 128B rows)
    const int laneA_row = lane & 15;
    const uint32_t baseA = (uint32_t)(((warp_m * 64 + laneA_row) << 7) + ((lane >> 4) << 4));
    const uint32_t xorA = (uint32_t)((laneA_row & 7) << 4);
    const int rowB = warp_n * 32 + ((lane >> 4) << 3) + (lane & 7);
    const uint32_t baseB = (uint32_t)((rowB << 7) + (((lane >> 3) & 1) << 4));
    const uint32_t xorB = (uint32_t)((rowB & 7) << 4);

    float c[4][4][4];

    // =============== Phase A: normalized-label gram (K=128, 2 chunks) ===============
    #pragma unroll
    for (int mf = 0; mf < 4; mf++)
        #pragma unroll
        for (int nf = 0; nf < 4; nf++)
            #pragma unroll
            for (int r = 0; r < 4; r++) c[mf][nf][r] = 0.0f;

    {
        const __half* Ai = g_lab_h + (size_t)i0 * CDIM;
        const __half* Bj = g_lab_h + (size_t)j0 * CDIM;
        cpasync_tile(Ai, CDIM, 0, sb, tid);
        cpasync_tile(Bj, CDIM, 0, sb + 16384, tid);
        CP_COMMIT();
        CP_WAIT0();
        __syncthreads();
        #pragma unroll
        for (int ch = 0; ch < 2; ch++) {
            if (ch + 1 < 2) {
                uint32_t nb = sb + ((ch + 1) & 1) * 32768;
                cpasync_tile(Ai, CDIM, (ch + 1) * 64, nb, tid);
                cpasync_tile(Bj, CDIM, (ch + 1) * 64, nb + 16384, tid);
                CP_COMMIT();
            }
            uint32_t sA = sb + (ch & 1) * 32768;
            uint32_t sB = sA + 16384;
            #pragma unroll
            for (int ks = 0; ks < 4; ks++) {
                uint4 a[4];
                #pragma unroll
                for (int mf = 0; mf < 4; mf++)
                    a[mf] = ldsm_x4(sA + ((baseA + mf * 2048 + ks * 32) ^ xorA));
                uint4 b0 = ldsm_x4(sB + ((baseB + ks * 32) ^ xorB));
                uint4 b1 = ldsm_x4(sB + ((baseB + 2048 + ks * 32) ^ xorB));
                #pragma unroll
                for (int mf = 0; mf < 4; mf++) {
                    mma16(c[mf][0], a[mf], b0.x, b0.y);
                    mma16(c[mf][1], a[mf], b0.z, b0.w);
                    mma16(c[mf][2], a[mf], b1.x, b1.y);
                    mma16(c[mf][3], a[mf], b1.z, b1.w);
                }
            }
            if (ch + 1 < 2) {
                CP_WAIT0();
                __syncthreads();
            }
        }
    }

    // epilogue A: min/max reduce + stash sim tile (thread-private, conflict-free)
    {
        float lmin = 3.4e38f, lmax = -3.4e38f;
        #pragma unroll
        for (int mf = 0; mf < 4; mf++) {
            #pragma unroll
            for (int nf = 0; nf < 4; nf++) {
                float v0 = c[mf][nf][0], v1 = c[mf][nf][1];
                float v2 = c[mf][nf][2], v3 = c[mf][nf][3];
                lmin = fminf(lmin, fminf(fminf(v0, v1), fminf(v2, v3)));
                lmax = fmaxf(lmax, fmaxf(fmaxf(v0, v1), fmaxf(v2, v3)));
                int idx0 = (mf * 4 + nf) * 2;
                __half2 h01 = __floats2half2_rn(v0, v1);
                __half2 h23 = __floats2half2_rn(v2, v3);
                stash[idx0 * 256 + tid]       = *(unsigned*)&h01;
                stash[(idx0 + 1) * 256 + tid] = *(unsigned*)&h23;
            }
        }
        #pragma unroll
        for (int off = 16; off; off >>= 1) {
            lmin = fminf(lmin, __shfl_xor_sync(0xffffffffu, lmin, off));
            lmax = fmaxf(lmax, __shfl_xor_sync(0xffffffffu, lmax, off));
        }
        if (lane == 0) {
            atomicMin(&g_smin_enc, fenc(lmin));
            atomicMax(&g_smax_enc, fenc(lmax));
        }
    }

    // =============== Phase B: output gram (K=256, 4 chunks) ===============
    #pragma unroll
    for (int mf = 0; mf < 4; mf++)
        #pragma unroll
        for (int nf = 0; nf < 4; nf++)
            #pragma unroll
            for (int r = 0; r < 4; r++) c[mf][nf][r] = 0.0f;

    {
        const __half* Ai = g_out_h + (size_t)i0 * DDIM;
        const __half* Bj = g_out_h + (size_t)j0 * DDIM;
        cpasync_tile(Ai, DDIM, 0, sb, tid);
        cpasync_tile(Bj, DDIM, 0, sb + 16384, tid);
        CP_COMMIT();
        CP_WAIT0();
        __syncthreads();
        #pragma unroll 1
        for (int ch = 0; ch < 4; ch++) {
            if (ch + 1 < 4) {
                uint32_t nb = sb + ((ch + 1) & 1) * 32768;
                cpasync_tile(Ai, DDIM, (ch + 1) * 64, nb, tid);
                cpasync_tile(Bj, DDIM, (ch + 1) * 64, nb + 16384, tid);
                CP_COMMIT();
            }
            uint32_t sA = sb + (ch & 1) * 32768;
            uint32_t sB = sA + 16384;
            #pragma unroll
            for (int ks = 0; ks < 4; ks++) {
                uint4 a[4];
                #pragma unroll
                for (int mf = 0; mf < 4; mf++)
                    a[mf] = ldsm_x4(sA + ((baseA + mf * 2048 + ks * 32) ^ xorA));
                uint4 b0 = ldsm_x4(sB + ((baseB + ks * 32) ^ xorB));
                uint4 b1 = ldsm_x4(sB + ((baseB + 2048 + ks * 32) ^ xorB));
                #pragma unroll
                for (int mf = 0; mf < 4; mf++) {
                    mma16(c[mf][0], a[mf], b0.x, b0.y);
                    mma16(c[mf][1], a[mf], b0.z, b0.w);
                    mma16(c[mf][2], a[mf], b1.x, b1.y);
                    mma16(c[mf][3], a[mf], b1.z, b1.w);
                }
            }
            if (ch + 1 < 4) {
                CP_WAIT0();
                __syncthreads();
            }
        }
    }

    // epilogue B: eud + packed (sim|eud) store, UPPER TILE ONLY (no mirror)
    {
        float lemax = 0.0f;
        #pragma unroll
        for (int mf = 0; mf < 4; mf++) {
            int il = warp_m * 64 + mf * 16 + g;
            float q0 = s_sqi[il], q1 = s_sqi[il + 8];
            #pragma unroll
            for (int nf = 0; nf < 4; nf++) {
                int jl = warp_n * 32 + nf * 8 + 2 * tig;
                float r0 = s_sqj[jl], r1 = s_sqj[jl + 1];
                float d0 = q0 + r0 - 2.0f * c[mf][nf][0];
                float d1 = q0 + r1 - 2.0f * c[mf][nf][1];
                float d2_ = q1 + r0 - 2.0f * c[mf][nf][2];
                float d3 = q1 + r1 - 2.0f * c[mf][nf][3];
                float v0 = (d0 > 0.0f) ? sqrtf(d0) : 0.0f;
                float v1 = (d1 > 0.0f) ? sqrtf(d1) : 0.0f;
                float v2 = (d2_ > 0.0f) ? sqrtf(d2_) : 0.0f;
                float v3 = (d3 > 0.0f) ? sqrtf(d3) : 0.0f;
                if (i0 + il == j0 + jl) v0 = 0.0f;
                if (i0 + il == j0 + jl + 1) v1 = 0.0f;
                if (i0 + il + 8 == j0 + jl) v2 = 0.0f;
                if (i0 + il + 8 == j0 + jl + 1) v3 = 0.0f;
                lemax = fmaxf(lemax, fmaxf(fmaxf(v0, v1), fmaxf(v2, v3)));

                int idx0 = (mf * 4 + nf) * 2;
                unsigned sp01 = stash[idx0 * 256 + tid];
                unsigned sp23 = stash[(idx0 + 1) * 256 + tid];
                unsigned u0 = pack_se(sp01, v0);
                unsigned u1 = pack_se(sp01 >> 16, v1);
                unsigned u2 = pack_se(sp23, v2);
                unsigned u3 = pack_se(sp23 >> 16, v3);

                *(uint2*)&g_se[(size_t)(i0 + il) * BSZ + j0 + jl]     = make_uint2(u0, u1);
                *(uint2*)&g_se[(size_t)(i0 + il + 8) * BSZ + j0 + jl] = make_uint2(u2, u3);
            }
        }
        #pragma unroll
        for (int off = 16; off; off >>= 1)
            lemax = fmaxf(lemax, __shfl_xor_sync(0xffffffffu, lemax, off));
        if (lane == 0) atomicMax(&g_emax_enc, fenc(lemax));
    }
}

// ---------------- kernel 3: tile loss — each exp used for row AND col partials ----------------
__global__ __launch_bounds__(256) void loss_tile_kernel() {
    int bi, bj;
    tri_decode(blockIdx.x, bi, bj);
    const int i0 = bi * TILE, j0 = bj * TILE;
    const int t = threadIdx.x;
    const int cc = t & 31;          // uint4 column group (cols cc*4 .. cc*4+3)
    const int rw = t >> 5;          // warp id: rows rw*16 .. rw*16+15

    const float L2E = 1.4426950408889634f;
    const float smin = fdec(g_smin_enc);
    const float smax = fdec(g_smax_enc);
    const float emax = fdec(g_emax_enc);
    const float c1 = L2E / (smax - smin);
    const float c0 = -smin * c1;
    const float c2 = L2E / emax;
    const float sthr = smin + 0.5f * (smax - smin);

    __shared__ float2 scol[8][128];

    float cp[4] = {0, 0, 0, 0}, cn[4] = {0, 0, 0, 0};

    #pragma unroll 1
    for (int r = 0; r < 16; r++) {
        const int row = rw * 16 + r;
        uint4 v = *(const uint4*)&g_se[(size_t)(i0 + row) * BSZ + j0 + cc * 4];
        float rp = 0.0f, rn = 0.0f;
        unsigned uu[4] = {v.x, v.y, v.z, v.w};
        #pragma unroll
        for (int x = 0; x < 4; x++) {
            float2 f = __half22float2(*(__half2*)&uu[x]);   // f.x = sim, f.y = eud
            float d = fmaf(f.y, c2, fmaf(f.x, c1, c0));
            bool pos = f.x > sthr;
            float val = exp2f(pos ? d : (L2E - d));
            float vp = pos ? val : 0.0f;
            float vn = pos ? 0.0f : val;
            rp += vp; rn += vn;
            cp[x] += vp; cn[x] += vn;
        }
        #pragma unroll
        for (int off = 16; off; off >>= 1) {
            rp += __shfl_xor_sync(0xffffffffu, rp, off);
            rn += __shfl_xor_sync(0xffffffffu, rn, off);
        }
        if (cc == 0)
            g_part[(size_t)(i0 + row) * NTILE + bj] = make_float2(rp, rn);
    }

    // cross-warp reduce of column partials
    #pragma unroll
    for (int x = 0; x < 4; x++) scol[rw][cc * 4 + x] = make_float2(cp[x], cn[x]);
    __syncthreads();
    if (bi != bj && t < 128) {
        float p = 0.0f, n = 0.0f;
        #pragma unroll
        for (int w = 0; w < 8; w++) {
            float2 v = scol[w][t];
            p += v.x; n += v.y;
        }
        g_part[(size_t)(j0 + t) * NTILE + bi] = make_float2(p, n);
    }
}

// ---------------- kernel 4: per-row reduce of partials -> rowloss ----------------
__global__ __launch_bounds__(128) void rowreduce_kernel() {
    const int row = blockIdx.x * 128 + threadIdx.x;
    const float2* p = &g_part[(size_t)row * NTILE];
    float P = 0.0f, N = 0.0f;
    #pragma unroll
    for (int k = 0; k < NTILE; k++) {
        float2 v = p[k];
        P += v.x; N += v.y;
    }
    float lp = fmaxf(logf(P), 0.0f);   // log(0) = -inf -> clamped to 0
    float ln = fmaxf(logf(N), 0.0f);
    g_rowloss[row] = lp + ln;
}

// ---------------- kernel 5: deterministic final mean ----------------
__global__ __launch_bounds__(256) void final_kernel(float* __restrict__ out) {
    __shared__ float s[256];
    const int t = threadIdx.x;
    float a = 0.0f;
    for (int i = t; i < BSZ; i += 256) a += g_rowloss[i];
    s[t] = a;
    __syncthreads();
    #pragma unroll
    for (int o = 128; o; o >>= 1) {
        if (t < o) s[t] += s[t + o];
        __syncthreads();
    }
    if (t == 0) out[0] = s[0] * (1.0f / (float)BSZ);
}

// ---------------- launch ----------------
extern "C" void kernel_launch(void* const* d_in, const int* in_sizes, int n_in,
                              void* d_out, int out_size) {
    const float* outputs = (const float*)d_in[0];
    const float* labels  = (const float*)d_in[1];
    if (n_in >= 2 && in_sizes[0] == BSZ * CDIM && in_sizes[1] == BSZ * DDIM) {
        const float* tmp = outputs; outputs = labels; labels = tmp;
    }
    float* out = (float*)d_out;

    cudaFuncSetAttribute(gram_mma, cudaFuncAttributeMaxDynamicSharedMemorySize, SM_BYTES);

    init_kernel<<<1, 1>>>();
    rowprep_kernel<<<BSZ, 128>>>(outputs, labels);
    gram_mma<<<NPAIRS, 256, SM_BYTES>>>();
    loss_tile_kernel<<<NPAIRS, 256>>>();
    rowreduce_kernel<<<NTILE, 128>>>();
    final_kernel<<<1, 256>>>(out);
}